// round 5
// baseline (speedup 1.0000x reference)
#include <cuda_runtime.h>
#include <math.h>
#include <stdint.h>

#define BB 8
#define NN 1024
#define DD 256
#define HH 8
#define HD 32
#define ROWS (BB*NN)          // 8192
#define ELEMS (ROWS*DD)       // 2097152
#define SEG 4                 // cross-block key split
#define AG 4                  // in-block key split (groups)

typedef unsigned long long u64;

// -------- scratch (static device globals; no allocation) --------
__device__ float g_q[ELEMS];
__device__ float g_k[ELEMS];
__device__ float g_v[ELEMS];
__device__ float g_t[ELEMS];
__device__ float g_u[ELEMS];
__device__ float g_pacc[SEG * ELEMS];          // partial A@V sums
__device__ float g_pes[SEG * ROWS * HH];       // partial exp sums

// ---------- packed f32x2 helpers (SASS FFMA2; PTX-only path) ----------
__device__ __forceinline__ u64 pk(float x, float y) {
    u64 r; asm("mov.b64 %0, {%1, %2};" : "=l"(r) : "f"(x), "f"(y)); return r;
}
__device__ __forceinline__ void upk(float& x, float& y, u64 p) {
    asm("mov.b64 {%0, %1}, %2;" : "=f"(x), "=f"(y) : "l"(p));
}
__device__ __forceinline__ u64 f2fma(u64 a, u64 b, u64 c) {
    u64 d; asm("fma.rn.f32x2 %0, %1, %2, %3;" : "=l"(d) : "l"(a), "l"(b), "l"(c)); return d;
}
__device__ __forceinline__ u64 f2add(u64 a, u64 b) {
    u64 d; asm("add.rn.f32x2 %0, %1, %2;" : "=l"(d) : "l"(a), "l"(b)); return d;
}
__device__ __forceinline__ void lds2(u64& a, u64& b, uint32_t addr) {
    asm volatile("ld.shared.v2.b64 {%0, %1}, [%2];" : "=l"(a), "=l"(b) : "r"(addr));
}

// ---------------- GEMM: C[8192,256] = X[8192,256] @ W[256,256] + bias ----------------
// 64x128 tile, 256 threads, 4 rows x 8 cols per thread via FFMA2.
template<int MODE>
__global__ void __launch_bounds__(256) gemm_kernel(
    const float* __restrict__ X, const float* __restrict__ W,
    const float* __restrict__ bias, float* __restrict__ C,
    const int* __restrict__ lengths)
{
    __shared__ float As[16][68];
    __shared__ float Bs[16][128];

    const int tid  = threadIdx.x;
    const int brow = blockIdx.x * 64;
    const int bcol = blockIdx.y * 128;
    const int tx = tid & 15;
    const int ty = tid >> 4;

    if (MODE == 0) {
        const int blen = lengths[brow >> 10];
        if ((brow & 1023) >= blen) {
            float4 z = make_float4(0.f, 0.f, 0.f, 0.f);
            #pragma unroll
            for (int i = 0; i < 8; i++) {
                int idx = tid + i * 256;
                int r = idx >> 5, c4 = idx & 31;
                *(float4*)&C[(size_t)(brow + r) * DD + bcol + c4 * 4] = z;
            }
            return;
        }
    }

    u64 acc[4][4];
    #pragma unroll
    for (int i = 0; i < 4; i++)
        #pragma unroll
        for (int p = 0; p < 4; p++) acc[i][p] = 0ull;

    const uint32_t bs_base = (uint32_t)__cvta_generic_to_shared(&Bs[0][0]);

    for (int k0 = 0; k0 < DD; k0 += 16) {
        {
            int r  = tid >> 2;
            int kc = (tid & 3) << 2;
            float4 xv = *(const float4*)&X[(size_t)(brow + r) * DD + k0 + kc];
            As[kc+0][r] = xv.x; As[kc+1][r] = xv.y;
            As[kc+2][r] = xv.z; As[kc+3][r] = xv.w;
        }
        {
            #pragma unroll
            for (int i = 0; i < 2; i++) {
                int idx = tid + i * 256;
                int r = idx >> 5, c = (idx & 31) << 2;
                *(float4*)&Bs[r][c] = *(const float4*)&W[(size_t)(k0 + r) * DD + bcol + c];
            }
        }
        __syncthreads();

        #pragma unroll
        for (int kk = 0; kk < 16; kk++) {
            float4 a4 = *(const float4*)&As[kk][ty << 2];
            u64 bp0, bp1, bp2, bp3;
            uint32_t baddr = bs_base + (uint32_t)(kk * 128 + (tx << 2)) * 4u;
            lds2(bp0, bp1, baddr);
            lds2(bp2, bp3, baddr + 256u);
            u64 aa;
            aa = pk(a4.x, a4.x);
            acc[0][0]=f2fma(aa,bp0,acc[0][0]); acc[0][1]=f2fma(aa,bp1,acc[0][1]);
            acc[0][2]=f2fma(aa,bp2,acc[0][2]); acc[0][3]=f2fma(aa,bp3,acc[0][3]);
            aa = pk(a4.y, a4.y);
            acc[1][0]=f2fma(aa,bp0,acc[1][0]); acc[1][1]=f2fma(aa,bp1,acc[1][1]);
            acc[1][2]=f2fma(aa,bp2,acc[1][2]); acc[1][3]=f2fma(aa,bp3,acc[1][3]);
            aa = pk(a4.z, a4.z);
            acc[2][0]=f2fma(aa,bp0,acc[2][0]); acc[2][1]=f2fma(aa,bp1,acc[2][1]);
            acc[2][2]=f2fma(aa,bp2,acc[2][2]); acc[2][3]=f2fma(aa,bp3,acc[2][3]);
            aa = pk(a4.w, a4.w);
            acc[3][0]=f2fma(aa,bp0,acc[3][0]); acc[3][1]=f2fma(aa,bp1,acc[3][1]);
            acc[3][2]=f2fma(aa,bp2,acc[3][2]); acc[3][3]=f2fma(aa,bp3,acc[3][3]);
        }
        __syncthreads();
    }

    const int c0 = bcol + (tx << 2);
    const int c1 = bcol + 64 + (tx << 2);
    float4 bv0 = *(const float4*)&bias[c0];
    float4 bv1 = *(const float4*)&bias[c1];

    #pragma unroll
    for (int i = 0; i < 4; i++) {
        int gr = brow + (ty << 2) + i;
        int bidx = gr >> 10;
        int nidx = gr & 1023;
        float4 o0, o1;
        upk(o0.x, o0.y, acc[i][0]); upk(o0.z, o0.w, acc[i][1]);
        upk(o1.x, o1.y, acc[i][2]); upk(o1.z, o1.w, acc[i][3]);
        o0.x += bv0.x; o0.y += bv0.y; o0.z += bv0.z; o0.w += bv0.w;
        o1.x += bv1.x; o1.y += bv1.y; o1.z += bv1.z; o1.w += bv1.w;
        if (MODE == 0) {
            if (nidx >= lengths[bidx]) {
                o0 = make_float4(0.f,0.f,0.f,0.f);
                o1 = make_float4(0.f,0.f,0.f,0.f);
            }
        } else {
            float4 r0 = *(const float4*)&X[(size_t)gr * DD + c0];
            float4 r1 = *(const float4*)&X[(size_t)gr * DD + c1];
            o0.x = r0.x + fmaxf(o0.x, 0.f); o0.y = r0.y + fmaxf(o0.y, 0.f);
            o0.z = r0.z + fmaxf(o0.z, 0.f); o0.w = r0.w + fmaxf(o0.w, 0.f);
            o1.x = r1.x + fmaxf(o1.x, 0.f); o1.y = r1.y + fmaxf(o1.y, 0.f);
            o1.z = r1.z + fmaxf(o1.z, 0.f); o1.w = r1.w + fmaxf(o1.w, 0.f);
        }
        *(float4*)&C[(size_t)gr * DD + c0] = o0;
        *(float4*)&C[(size_t)gr * DD + c1] = o1;
    }
}

// ---------------- Attention partial: grid (N/128, H, B*SEG) ----------------
// Block (qt,h,b,seg): keys in [seg slice of [0,len)), further split over 4 groups.
// Writes partial (esum, acc32) per (q-row, head) to global scratch.
__global__ void __launch_bounds__(512) attn_kernel(
    const float* __restrict__ q, const float* __restrict__ k,
    const float* __restrict__ v, const int* __restrict__ lengths,
    float* __restrict__ pacc, float* __restrict__ pes)
{
    extern __shared__ float sm[];
    const int bz = blockIdx.z;
    const int b = bz >> 2;           // bz / SEG
    const int seg = bz & 3;          // bz % SEG
    const int h = blockIdx.y;
    const int len = lengths[b];
    const int tid = threadIdx.x;
    const int g = tid >> 7;
    const int gtid = tid & 127;
    const int n = blockIdx.x * 128 + gtid;

    if (blockIdx.x * 128 >= len) return;   // combine zeroes masked rows

    float* ks = sm + g * 4096;
    float* vs = ks + 2048;
    const uint32_t ks_base = (uint32_t)__cvta_generic_to_shared(ks);
    const uint32_t vs_base = (uint32_t)__cvta_generic_to_shared(vs);

    const float* qrow = q + ((size_t)b * NN + n) * DD + h * HD;
    u64 qp[16];
    #pragma unroll
    for (int j = 0; j < HD; j += 4) {
        float4 t = *(const float4*)&qrow[j];
        qp[j/2]     = pk(t.x, t.y);
        qp[j/2 + 1] = pk(t.z, t.w);
    }

    u64 acc2[16];
    #pragma unroll
    for (int j = 0; j < 16; j++) acc2[j] = 0ull;
    float esum = 0.f;
    const bool active = (n < len);

    // segment range, then group range within it
    const int ssLen = (len + SEG - 1) / SEG;
    const int ss0 = seg * ssLen;
    const int ss1 = min(ss0 + ssLen, len);
    const int gl = (ss1 - ss0 + AG - 1) >> 2;
    const int s0 = ss0 + g * gl;
    const int s1 = (ss1 < s0 + gl) ? ss1 : (s0 + gl);

    const float* kbase = k + (size_t)b * NN * DD + h * HD;
    const float* vbase = v + (size_t)b * NN * DD + h * HD;

    for (int m0 = s0; m0 < s1; m0 += 64) {
        asm volatile("bar.sync %0, 128;" :: "r"(g + 1) : "memory");
        #pragma unroll
        for (int i = 0; i < 4; i++) {
            int idx = gtid + i * 128;
            int r = idx >> 3;
            int c = (idx & 7) << 2;
            int row = m0 + r;
            if (row >= s1) row = s1 - 1;     // clamp in-bounds; unused rows
            size_t off = (size_t)row * DD + c;
            *(float4*)&ks[r * 32 + c] = *(const float4*)&kbase[off];
            *(float4*)&vs[r * 32 + c] = *(const float4*)&vbase[off];
        }
        asm volatile("bar.sync %0, 128;" :: "r"(g + 1) : "memory");

        const int mEnd = min(64, s1 - m0);
        if (active) {
            uint32_t ka = ks_base, va = vs_base;
            for (int mm = 0; mm < mEnd; mm++) {
                u64 kp[16];
                #pragma unroll
                for (int j = 0; j < 8; j++) lds2(kp[2*j], kp[2*j+1], ka + j * 16u);
                u64 c0 = 0ull, c1 = 0ull, c2 = 0ull, c3 = 0ull;
                #pragma unroll
                for (int j = 0; j < 4; j++) {
                    c0 = f2fma(qp[4*j+0], kp[4*j+0], c0);
                    c1 = f2fma(qp[4*j+1], kp[4*j+1], c1);
                    c2 = f2fma(qp[4*j+2], kp[4*j+2], c2);
                    c3 = f2fma(qp[4*j+3], kp[4*j+3], c3);
                }
                u64 sp = f2add(f2add(c0, c1), f2add(c2, c3));
                float sx, sy; upk(sx, sy, sp);
                float e = __expf((sx + sy) * 0.0625f);   // 1/sqrt(DV) = 1/16
                esum += e;
                u64 ep = pk(e, e);
                u64 vp[16];
                #pragma unroll
                for (int j = 0; j < 8; j++) lds2(vp[2*j], vp[2*j+1], va + j * 16u);
                #pragma unroll
                for (int j = 0; j < 16; j++) acc2[j] = f2fma(ep, vp[j], acc2[j]);
                ka += 128u; va += 128u;
            }
        }
    }

    // ---- in-block combine of 4 groups, then write partials ----
    __syncthreads();
    float* cacc = sm;                      // [AG*128][32]
    float* ces  = sm + AG * 128 * 32;      // [AG*128]
    {
        float* dst = cacc + (size_t)(g * 128 + gtid) * 32;
        #pragma unroll
        for (int j = 0; j < 16; j += 2) {
            float4 t;
            upk(t.x, t.y, acc2[j]); upk(t.z, t.w, acc2[j+1]);
            *(float4*)&dst[j * 2] = t;
        }
        ces[g * 128 + gtid] = active ? esum : 0.f;
    }
    __syncthreads();
    if (g == 0 && active) {
        float tot = ces[gtid] + ces[128 + gtid] + ces[256 + gtid] + ces[384 + gtid];
        pes[(((size_t)seg * BB + b) * NN + n) * HH + h] = tot;
        const float* a0 = cacc + (size_t)(0 * 128 + gtid) * 32;
        const float* a1 = cacc + (size_t)(1 * 128 + gtid) * 32;
        const float* a2 = cacc + (size_t)(2 * 128 + gtid) * 32;
        const float* a3 = cacc + (size_t)(3 * 128 + gtid) * 32;
        float* pdst = pacc + (size_t)seg * ELEMS + ((size_t)b * NN + n) * DD + h * HD;
        #pragma unroll
        for (int j = 0; j < HD; j += 4) {
            float4 x0 = *(const float4*)&a0[j];
            float4 x1 = *(const float4*)&a1[j];
            float4 x2 = *(const float4*)&a2[j];
            float4 x3 = *(const float4*)&a3[j];
            float4 t;
            t.x = (x0.x + x1.x) + (x2.x + x3.x);
            t.y = (x0.y + x1.y) + (x2.y + x3.y);
            t.z = (x0.z + x1.z) + (x2.z + x3.z);
            t.w = (x0.w + x1.w) + (x2.w + x3.w);
            *(float4*)&pdst[j] = t;
        }
    }
}

// ---------------- combine SEG partials + residual + mask + LayerNorm, fused ----------------
__global__ void __launch_bounds__(256) combine_ln_kernel(
    const float* __restrict__ q, const float* __restrict__ pacc,
    const float* __restrict__ pes, const int* __restrict__ lengths,
    const float* __restrict__ g, const float* __restrict__ b, float* __restrict__ y)
{
    const int row = blockIdx.x;
    const int t = threadIdx.x;
    const int bidx = row >> 10;
    const int nidx = row & 1023;
    const int len = lengths[bidx];
    __shared__ float sred[8];

    float val = 0.f;
    if (nidx < len) {
        const int h = t >> 5;
        float es = 0.f, ac = 0.f;
        #pragma unroll
        for (int s = 0; s < SEG; s++) {
            es += pes[(((size_t)s * BB + bidx) * NN + nidx) * HH + h];
            ac += pacc[(size_t)s * ELEMS + (size_t)row * DD + t];
        }
        val = q[(size_t)row * DD + t] + ac / (es + 1e-15f);
    }

    float s = val;
    #pragma unroll
    for (int o = 16; o > 0; o >>= 1) s += __shfl_xor_sync(0xFFFFFFFFu, s, o);
    if ((t & 31) == 0) sred[t >> 5] = s;
    __syncthreads();
    float mu = 0.f;
    #pragma unroll
    for (int i = 0; i < 8; i++) mu += sred[i];
    mu *= (1.f / 256.f);

    float d = val - mu;
    float sq = d * d;
    #pragma unroll
    for (int o = 16; o > 0; o >>= 1) sq += __shfl_xor_sync(0xFFFFFFFFu, sq, o);
    __syncthreads();
    if ((t & 31) == 0) sred[t >> 5] = sq;
    __syncthreads();
    float var = 0.f;
    #pragma unroll
    for (int i = 0; i < 8; i++) var += sred[i];
    var *= (1.f / 256.f);

    float r = rsqrtf(var + 1e-5f);
    y[(size_t)row * DD + t] = d * r * g[t] + b[t];
}

// ---------------- plain LayerNorm ----------------
__global__ void __launch_bounds__(256) ln_kernel(
    const float* __restrict__ x, const float* __restrict__ g,
    const float* __restrict__ b, float* __restrict__ y)
{
    const int row = blockIdx.x;
    const int t = threadIdx.x;
    __shared__ float sred[8];

    float v = x[(size_t)row * DD + t];

    float s = v;
    #pragma unroll
    for (int o = 16; o > 0; o >>= 1) s += __shfl_xor_sync(0xFFFFFFFFu, s, o);
    if ((t & 31) == 0) sred[t >> 5] = s;
    __syncthreads();
    float mu = 0.f;
    #pragma unroll
    for (int i = 0; i < 8; i++) mu += sred[i];
    mu *= (1.f / 256.f);

    float d = v - mu;
    float sq = d * d;
    #pragma unroll
    for (int o = 16; o > 0; o >>= 1) sq += __shfl_xor_sync(0xFFFFFFFFu, sq, o);
    __syncthreads();
    if ((t & 31) == 0) sred[t >> 5] = sq;
    __syncthreads();
    float var = 0.f;
    #pragma unroll
    for (int i = 0; i < 8; i++) var += sred[i];
    var *= (1.f / 256.f);

    float r = rsqrtf(var + 1e-5f);
    y[(size_t)row * DD + t] = d * r * g[t] + b[t];
}

// ---------------- launch ----------------
extern "C" void kernel_launch(void* const* d_in, const int* in_sizes, int n_in,
                              void* d_out, int out_size)
{
    const float* Q       = (const float*)d_in[0];
    const float* K       = (const float*)d_in[1];
    const int*   lengths = (const int*)  d_in[2];
    const float* Wq      = (const float*)d_in[3];
    const float* bq      = (const float*)d_in[4];
    const float* Wk      = (const float*)d_in[5];
    const float* bk      = (const float*)d_in[6];
    const float* Wv      = (const float*)d_in[7];
    const float* bv      = (const float*)d_in[8];
    const float* Wo      = (const float*)d_in[9];
    const float* bo      = (const float*)d_in[10];
    const float* g0      = (const float*)d_in[11];
    const float* b0      = (const float*)d_in[12];
    const float* g1      = (const float*)d_in[13];
    const float* b1      = (const float*)d_in[14];

    float *sq, *sk, *sv, *st, *su, *pacc, *pes;
    cudaGetSymbolAddress((void**)&sq, g_q);
    cudaGetSymbolAddress((void**)&sk, g_k);
    cudaGetSymbolAddress((void**)&sv, g_v);
    cudaGetSymbolAddress((void**)&st, g_t);
    cudaGetSymbolAddress((void**)&su, g_u);
    cudaGetSymbolAddress((void**)&pacc, g_pacc);
    cudaGetSymbolAddress((void**)&pes, g_pes);

    dim3 gg(ROWS / 64, DD / 128);

    gemm_kernel<0><<<gg, 256>>>(Q, Wq, bq, sq, lengths);
    gemm_kernel<0><<<gg, 256>>>(K, Wk, bk, sk, lengths);
    gemm_kernel<0><<<gg, 256>>>(K, Wv, bv, sv, lengths);

    const int ATTN_SMEM = (AG * 4096 + AG * 128) * (int)sizeof(float);
    static int attn_cfg = 0;
    if (!attn_cfg) {
        cudaFuncSetAttribute(attn_kernel, cudaFuncAttributeMaxDynamicSharedMemorySize, ATTN_SMEM);
        attn_cfg = 1;
    }
    attn_kernel<<<dim3(NN / 128, HH, BB * SEG), 512, ATTN_SMEM>>>(sq, sk, sv, lengths, pacc, pes);

    combine_ln_kernel<<<ROWS, 256>>>(sq, pacc, pes, lengths, g0, b0, st);

    gemm_kernel<1><<<gg, 256>>>(st, Wo, bo, su, nullptr);

    ln_kernel<<<ROWS, 256>>>(su, g1, b1, (float*)d_out);
}

// round 6
// speedup vs baseline: 1.4621x; 1.4621x over previous
#include <cuda_runtime.h>
#include <cuda_bf16.h>
#include <math.h>
#include <stdint.h>

#define BB 8
#define NN 1024
#define DD 256
#define HH 8
#define HD 32
#define ROWS (BB*NN)          // 8192
#define ELEMS (ROWS*DD)       // 2097152
#define AG 4

typedef unsigned long long u64;

// -------- scratch (static device globals; no allocation) --------
__device__ float g_q[ELEMS];
__device__ float g_k[ELEMS];
__device__ float g_v[ELEMS];
__device__ float g_o[ELEMS];
__device__ float g_t[ELEMS];
__device__ float g_u[ELEMS];

__device__ __nv_bfloat16 g_qih[ELEMS];   // Q input split
__device__ __nv_bfloat16 g_qil[ELEMS];
__device__ __nv_bfloat16 g_kih[ELEMS];   // K input split
__device__ __nv_bfloat16 g_kil[ELEMS];
__device__ __nv_bfloat16 g_th[ELEMS];    // ln0 output split
__device__ __nv_bfloat16 g_tl[ELEMS];

#define WSZ (DD*DD)
__device__ __nv_bfloat16 g_wqh[WSZ]; __device__ __nv_bfloat16 g_wql[WSZ];
__device__ __nv_bfloat16 g_wkh[WSZ]; __device__ __nv_bfloat16 g_wkl[WSZ];
__device__ __nv_bfloat16 g_wvh[WSZ]; __device__ __nv_bfloat16 g_wvl[WSZ];
__device__ __nv_bfloat16 g_woh[WSZ]; __device__ __nv_bfloat16 g_wol[WSZ];

// ---------- packed f32x2 helpers ----------
__device__ __forceinline__ u64 pk(float x, float y) {
    u64 r; asm("mov.b64 %0, {%1, %2};" : "=l"(r) : "f"(x), "f"(y)); return r;
}
__device__ __forceinline__ void upk(float& x, float& y, u64 p) {
    asm("mov.b64 {%0, %1}, %2;" : "=f"(x), "=f"(y) : "l"(p));
}
__device__ __forceinline__ u64 f2fma(u64 a, u64 b, u64 c) {
    u64 d; asm("fma.rn.f32x2 %0, %1, %2, %3;" : "=l"(d) : "l"(a), "l"(b), "l"(c)); return d;
}
__device__ __forceinline__ u64 f2add(u64 a, u64 b) {
    u64 d; asm("add.rn.f32x2 %0, %1, %2;" : "=l"(d) : "l"(a), "l"(b)); return d;
}
__device__ __forceinline__ void lds2(u64& a, u64& b, uint32_t addr) {
    asm volatile("ld.shared.v2.b64 {%0, %1}, [%2];" : "=l"(a), "=l"(b) : "r"(addr));
}

// ---------- HMMA helpers ----------
__device__ __forceinline__ void ldmx4(uint32_t* r, uint32_t addr) {
    asm volatile("ldmatrix.sync.aligned.m8n8.x4.shared.b16 {%0,%1,%2,%3}, [%4];"
                 : "=r"(r[0]), "=r"(r[1]), "=r"(r[2]), "=r"(r[3]) : "r"(addr));
}
__device__ __forceinline__ void mma_bf16(float* c, const uint32_t* a, uint32_t b0, uint32_t b1) {
    asm volatile(
        "mma.sync.aligned.m16n8k16.row.col.f32.bf16.bf16.f32 "
        "{%0,%1,%2,%3}, {%4,%5,%6,%7}, {%8,%9}, {%0,%1,%2,%3};"
        : "+f"(c[0]), "+f"(c[1]), "+f"(c[2]), "+f"(c[3])
        : "r"(a[0]), "r"(a[1]), "r"(a[2]), "r"(a[3]), "r"(b0), "r"(b1));
}

// ================= split kernels =================
__global__ void __launch_bounds__(256) split_kernel(
    const float4* __restrict__ x, uint2* __restrict__ hi, uint2* __restrict__ lo, int n4)
{
    int i = blockIdx.x * 256 + threadIdx.x;
    if (i >= n4) return;
    float4 v = x[i];
    __nv_bfloat16 h0 = __float2bfloat16(v.x), h1 = __float2bfloat16(v.y);
    __nv_bfloat16 h2 = __float2bfloat16(v.z), h3 = __float2bfloat16(v.w);
    __nv_bfloat16 l0 = __float2bfloat16(v.x - __bfloat162float(h0));
    __nv_bfloat16 l1 = __float2bfloat16(v.y - __bfloat162float(h1));
    __nv_bfloat16 l2 = __float2bfloat16(v.z - __bfloat162float(h2));
    __nv_bfloat16 l3 = __float2bfloat16(v.w - __bfloat162float(h3));
    __nv_bfloat162 hp0 = __halves2bfloat162(h0, h1), hp1 = __halves2bfloat162(h2, h3);
    __nv_bfloat162 lp0 = __halves2bfloat162(l0, l1), lp1 = __halves2bfloat162(l2, l3);
    uint2 hu, lu;
    hu.x = *(uint32_t*)&hp0; hu.y = *(uint32_t*)&hp1;
    lu.x = *(uint32_t*)&lp0; lu.y = *(uint32_t*)&lp1;
    hi[i] = hu; lo[i] = lu;
}

// Wt[n,k] = W[k,n], split hi/lo
__global__ void __launch_bounds__(256) wsplit_kernel(
    const float* __restrict__ W, __nv_bfloat16* __restrict__ th, __nv_bfloat16* __restrict__ tl)
{
    int n = blockIdx.x, k = threadIdx.x;
    float w = W[k * DD + n];
    __nv_bfloat16 h = __float2bfloat16(w);
    __nv_bfloat16 l = __float2bfloat16(w - __bfloat162float(h));
    th[n * DD + k] = h; tl[n * DD + k] = l;
}

// ================= HMMA GEMM: C[8192,256] = A @ W + epilogue =================
// A split (Ah,Al) bf16 row-major [8192,256]; W split transposed (Bh,Bl)[n,k] bf16.
// bf16x3: AhBh + AhBl + AlBh. Tile 128x128, 8 warps (2x4), warp tile 64x32.
// MODE 0: +bias, zero rows n>=len (skip fully masked tiles). MODE 1: res + relu(acc+bias).
#define PSTR 72   // padded smem row stride (bf16 elems)
template<int MODE>
__global__ void __launch_bounds__(256) hgemm_kernel(
    const __nv_bfloat16* __restrict__ Ah_, const __nv_bfloat16* __restrict__ Al_,
    const __nv_bfloat16* __restrict__ Bh_, const __nv_bfloat16* __restrict__ Bl_,
    const float* __restrict__ bias, const float* __restrict__ res,
    float* __restrict__ C, const int* __restrict__ lengths)
{
    extern __shared__ char smc[];
    const int tid = threadIdx.x, wid = tid >> 5, lane = tid & 31;
    const int brow = blockIdx.x * 128, bcol = blockIdx.y * 128;
    const int wm = wid & 1, wn = wid >> 1;

    if (MODE == 0) {
        const int blen = lengths[brow >> 10];
        if ((brow & 1023) >= blen) {
            float4 z = make_float4(0.f, 0.f, 0.f, 0.f);
            #pragma unroll
            for (int i = 0; i < 16; i++) {
                int idx = tid + i * 256;              // 128 rows x 32 float4
                int r = idx >> 5, c4 = idx & 31;
                *(float4*)&C[(size_t)(brow + r) * DD + bcol + c4 * 4] = z;
            }
            return;
        }
    }

    __nv_bfloat16* sAh = (__nv_bfloat16*)smc;
    __nv_bfloat16* sAl = sAh + 128 * PSTR;
    __nv_bfloat16* sBh = sAl + 128 * PSTR;
    __nv_bfloat16* sBl = sBh + 128 * PSTR;
    const uint32_t bAh = (uint32_t)__cvta_generic_to_shared(sAh);
    const uint32_t bAl = (uint32_t)__cvta_generic_to_shared(sAl);
    const uint32_t bBh = (uint32_t)__cvta_generic_to_shared(sBh);
    const uint32_t bBl = (uint32_t)__cvta_generic_to_shared(sBl);

    float acc[4][4][4];
    #pragma unroll
    for (int i = 0; i < 4; i++)
        #pragma unroll
        for (int j = 0; j < 4; j++)
            #pragma unroll
            for (int p = 0; p < 4; p++) acc[i][j][p] = 0.f;

    // per-lane ldmatrix element offsets
    const int aRow = wm * 64 + (lane & 15);
    const int aK   = (lane >> 4) * 8;
    const int bRow = wn * 32 + (lane & 7) + (lane >> 4) * 8;
    const int bK   = ((lane >> 3) & 1) * 8;

    const int ldr = tid >> 3;          // smem load row 0..31 (x4 iters -> 128)
    const int ldc = tid & 7;           // uint4 col 0..7

    for (int ch = 0; ch < 4; ch++) {
        const int kc0 = ch * 64;
        if (ch > 0) __syncthreads();
        #pragma unroll
        for (int i = 0; i < 4; i++) {
            int r = ldr + i * 32;
            size_t ga = (size_t)(brow + r) * DD + kc0 + ldc * 8;
            size_t gb = (size_t)(bcol + r) * DD + kc0 + ldc * 8;
            *(uint4*)&sAh[r * PSTR + ldc * 8] = *(const uint4*)(Ah_ + ga);
            *(uint4*)&sAl[r * PSTR + ldc * 8] = *(const uint4*)(Al_ + ga);
            *(uint4*)&sBh[r * PSTR + ldc * 8] = *(const uint4*)(Bh_ + gb);
            *(uint4*)&sBl[r * PSTR + ldc * 8] = *(const uint4*)(Bl_ + gb);
        }
        __syncthreads();

        #pragma unroll
        for (int ks = 0; ks < 4; ks++) {
            const int kk = ks * 16;
            uint32_t ah[4][4], al[4][4], bh[2][4], bl[2][4];
            #pragma unroll
            for (int mi = 0; mi < 4; mi++) {
                uint32_t off = (uint32_t)((aRow + mi * 16) * PSTR + kk + aK) * 2u;
                ldmx4(ah[mi], bAh + off);
                ldmx4(al[mi], bAl + off);
            }
            #pragma unroll
            for (int n2 = 0; n2 < 2; n2++) {
                uint32_t off = (uint32_t)((bRow + n2 * 16) * PSTR + kk + bK) * 2u;
                ldmx4(bh[n2], bBh + off);
                ldmx4(bl[n2], bBl + off);
            }
            #pragma unroll
            for (int mi = 0; mi < 4; mi++)
                #pragma unroll
                for (int ni = 0; ni < 4; ni++) {
                    uint32_t bh0 = bh[ni >> 1][(ni & 1) * 2], bh1 = bh[ni >> 1][(ni & 1) * 2 + 1];
                    uint32_t bl0 = bl[ni >> 1][(ni & 1) * 2], bl1 = bl[ni >> 1][(ni & 1) * 2 + 1];
                    mma_bf16(acc[mi][ni], ah[mi], bh0, bh1);
                    mma_bf16(acc[mi][ni], ah[mi], bl0, bl1);
                    mma_bf16(acc[mi][ni], al[mi], bh0, bh1);
                }
        }
    }

    // epilogue: frag c: rows l/4 (+8), cols 2(l%4) (+1)
    const int blen = (MODE == 0) ? lengths[brow >> 10] : 0;
    #pragma unroll
    for (int mi = 0; mi < 4; mi++) {
        int r0 = brow + wm * 64 + mi * 16 + (lane >> 2);
        int r1 = r0 + 8;
        #pragma unroll
        for (int ni = 0; ni < 4; ni++) {
            int col = bcol + wn * 32 + ni * 8 + (lane & 3) * 2;
            float b0 = bias[col], b1 = bias[col + 1];
            float c0 = acc[mi][ni][0] + b0, c1 = acc[mi][ni][1] + b1;
            float c2 = acc[mi][ni][2] + b0, c3 = acc[mi][ni][3] + b1;
            if (MODE == 0) {
                if ((r0 & 1023) >= blen) { c0 = 0.f; c1 = 0.f; }
                if ((r1 & 1023) >= blen) { c2 = 0.f; c3 = 0.f; }
            } else {
                float2 x0 = *(const float2*)&res[(size_t)r0 * DD + col];
                float2 x1 = *(const float2*)&res[(size_t)r1 * DD + col];
                c0 = x0.x + fmaxf(c0, 0.f); c1 = x0.y + fmaxf(c1, 0.f);
                c2 = x1.x + fmaxf(c2, 0.f); c3 = x1.y + fmaxf(c3, 0.f);
            }
            *(float2*)&C[(size_t)r0 * DD + col] = make_float2(c0, c1);
            *(float2*)&C[(size_t)r1 * DD + col] = make_float2(c2, c3);
        }
    }
}

// ---------------- Attention (round-4 proven version) ----------------
__global__ void __launch_bounds__(512) attn_kernel(
    const float* __restrict__ q, const float* __restrict__ k,
    const float* __restrict__ v, const int* __restrict__ lengths,
    float* __restrict__ o)
{
    extern __shared__ float sm[];
    const int b = blockIdx.z;
    const int h = blockIdx.y;
    const int len = lengths[b];
    const int tid = threadIdx.x;
    const int g = tid >> 7;
    const int gtid = tid & 127;
    const int n = blockIdx.x * 128 + gtid;

    float* orow = o + ((size_t)b * NN + n) * DD + h * HD;

    if (blockIdx.x * 128 >= len) {
        if (g == 0) {
            float4 z = make_float4(0.f, 0.f, 0.f, 0.f);
            #pragma unroll
            for (int j = 0; j < HD; j += 4) *(float4*)&orow[j] = z;
        }
        return;
    }

    float* ks = sm + g * 4096;
    float* vs = ks + 2048;
    const uint32_t ks_base = (uint32_t)__cvta_generic_to_shared(ks);
    const uint32_t vs_base = (uint32_t)__cvta_generic_to_shared(vs);

    const float* qrow = q + ((size_t)b * NN + n) * DD + h * HD;
    u64 qp[16];
    #pragma unroll
    for (int j = 0; j < HD; j += 4) {
        float4 t = *(const float4*)&qrow[j];
        qp[j/2]     = pk(t.x, t.y);
        qp[j/2 + 1] = pk(t.z, t.w);
    }

    u64 acc2[16];
    #pragma unroll
    for (int j = 0; j < 16; j++) acc2[j] = 0ull;
    float esum = 0.f;
    const bool active = (n < len);

    const int segLen = (len + AG - 1) >> 2;
    const int s0 = g * segLen;
    const int s1 = min(s0 + segLen, len);

    const float* kbase = k + (size_t)b * NN * DD + h * HD;
    const float* vbase = v + (size_t)b * NN * DD + h * HD;

    for (int m0 = s0; m0 < s1; m0 += 64) {
        asm volatile("bar.sync %0, 128;" :: "r"(g + 1) : "memory");
        #pragma unroll
        for (int i = 0; i < 4; i++) {
            int idx = gtid + i * 128;
            int r = idx >> 3;
            int c = (idx & 7) << 2;
            int row = m0 + r;
            if (row >= len) row = len - 1;
            size_t off = (size_t)row * DD + c;
            *(float4*)&ks[r * 32 + c] = *(const float4*)&kbase[off];
            *(float4*)&vs[r * 32 + c] = *(const float4*)&vbase[off];
        }
        asm volatile("bar.sync %0, 128;" :: "r"(g + 1) : "memory");

        const int mEnd = min(64, s1 - m0);
        if (active) {
            uint32_t ka = ks_base, va = vs_base;
            for (int mm = 0; mm < mEnd; mm++) {
                u64 kp[16];
                #pragma unroll
                for (int j = 0; j < 8; j++) lds2(kp[2*j], kp[2*j+1], ka + j * 16u);
                u64 c0 = 0ull, c1 = 0ull, c2 = 0ull, c3 = 0ull;
                #pragma unroll
                for (int j = 0; j < 4; j++) {
                    c0 = f2fma(qp[4*j+0], kp[4*j+0], c0);
                    c1 = f2fma(qp[4*j+1], kp[4*j+1], c1);
                    c2 = f2fma(qp[4*j+2], kp[4*j+2], c2);
                    c3 = f2fma(qp[4*j+3], kp[4*j+3], c3);
                }
                u64 sp = f2add(f2add(c0, c1), f2add(c2, c3));
                float sx, sy; upk(sx, sy, sp);
                float e = __expf((sx + sy) * 0.0625f);
                esum += e;
                u64 ep = pk(e, e);
                u64 vp[16];
                #pragma unroll
                for (int j = 0; j < 8; j++) lds2(vp[2*j], vp[2*j+1], va + j * 16u);
                #pragma unroll
                for (int j = 0; j < 16; j++) acc2[j] = f2fma(ep, vp[j], acc2[j]);
                ka += 128u; va += 128u;
            }
        }
    }

    __syncthreads();
    float* cacc = sm;
    float* ces  = sm + AG * 128 * 32;
    {
        float* dst = cacc + (size_t)(g * 128 + gtid) * 32;
        #pragma unroll
        for (int j = 0; j < 16; j += 2) {
            float4 t;
            upk(t.x, t.y, acc2[j]); upk(t.z, t.w, acc2[j+1]);
            *(float4*)&dst[j * 2] = t;
        }
        ces[g * 128 + gtid] = active ? esum : 0.f;
    }
    __syncthreads();
    if (g == 0) {
        float tot = ces[gtid] + ces[128 + gtid] + ces[256 + gtid] + ces[384 + gtid];
        float inv = active ? (1.f / (tot + 1e-15f)) : 0.f;
        const float* a0 = cacc + (size_t)(0 * 128 + gtid) * 32;
        const float* a1 = cacc + (size_t)(1 * 128 + gtid) * 32;
        const float* a2 = cacc + (size_t)(2 * 128 + gtid) * 32;
        const float* a3 = cacc + (size_t)(3 * 128 + gtid) * 32;
        #pragma unroll
        for (int j = 0; j < HD; j += 4) {
            float4 x0 = *(const float4*)&a0[j];
            float4 x1 = *(const float4*)&a1[j];
            float4 x2 = *(const float4*)&a2[j];
            float4 x3 = *(const float4*)&a3[j];
            float qx, qy, qz, qw;
            upk(qx, qy, qp[j/2]); upk(qz, qw, qp[j/2 + 1]);
            float4 t;
            t.x = active ? (qx + (x0.x + x1.x + x2.x + x3.x) * inv) : 0.f;
            t.y = active ? (qy + (x0.y + x1.y + x2.y + x3.y) * inv) : 0.f;
            t.z = active ? (qz + (x0.z + x1.z + x2.z + x3.z) * inv) : 0.f;
            t.w = active ? (qw + (x0.w + x1.w + x2.w + x3.w) * inv) : 0.f;
            *(float4*)&orow[j] = t;
        }
    }
}

// ---------------- LayerNorm (optionally emits bf16 hi/lo split) ----------------
template<bool SPLIT>
__global__ void __launch_bounds__(256) ln_kernel(
    const float* __restrict__ x, const float* __restrict__ g,
    const float* __restrict__ b, float* __restrict__ y,
    __nv_bfloat16* __restrict__ yh, __nv_bfloat16* __restrict__ yl)
{
    const int row = blockIdx.x;
    const int t = threadIdx.x;
    __shared__ float sred[8];

    float v = x[(size_t)row * DD + t];

    float s = v;
    #pragma unroll
    for (int o = 16; o > 0; o >>= 1) s += __shfl_xor_sync(0xFFFFFFFFu, s, o);
    if ((t & 31) == 0) sred[t >> 5] = s;
    __syncthreads();
    float mu = 0.f;
    #pragma unroll
    for (int i = 0; i < 8; i++) mu += sred[i];
    mu *= (1.f / 256.f);

    float d = v - mu;
    float sq = d * d;
    #pragma unroll
    for (int o = 16; o > 0; o >>= 1) sq += __shfl_xor_sync(0xFFFFFFFFu, sq, o);
    __syncthreads();
    if ((t & 31) == 0) sred[t >> 5] = sq;
    __syncthreads();
    float var = 0.f;
    #pragma unroll
    for (int i = 0; i < 8; i++) var += sred[i];
    var *= (1.f / 256.f);

    float r = rsqrtf(var + 1e-5f);
    float out = d * r * g[t] + b[t];
    y[(size_t)row * DD + t] = out;
    if (SPLIT) {
        __nv_bfloat16 h = __float2bfloat16(out);
        __nv_bfloat16 l = __float2bfloat16(out - __bfloat162float(h));
        yh[(size_t)row * DD + t] = h;
        yl[(size_t)row * DD + t] = l;
    }
}

// ---------------- launch ----------------
extern "C" void kernel_launch(void* const* d_in, const int* in_sizes, int n_in,
                              void* d_out, int out_size)
{
    const float* Q       = (const float*)d_in[0];
    const float* K       = (const float*)d_in[1];
    const int*   lengths = (const int*)  d_in[2];
    const float* Wq      = (const float*)d_in[3];
    const float* bq      = (const float*)d_in[4];
    const float* Wk      = (const float*)d_in[5];
    const float* bk      = (const float*)d_in[6];
    const float* Wv      = (const float*)d_in[7];
    const float* bv      = (const float*)d_in[8];
    const float* Wo      = (const float*)d_in[9];
    const float* bo      = (const float*)d_in[10];
    const float* g0      = (const float*)d_in[11];
    const float* b0      = (const float*)d_in[12];
    const float* g1      = (const float*)d_in[13];
    const float* b1      = (const float*)d_in[14];

    float *sq, *sk, *sv, *so, *st, *su;
    cudaGetSymbolAddress((void**)&sq, g_q);
    cudaGetSymbolAddress((void**)&sk, g_k);
    cudaGetSymbolAddress((void**)&sv, g_v);
    cudaGetSymbolAddress((void**)&so, g_o);
    cudaGetSymbolAddress((void**)&st, g_t);
    cudaGetSymbolAddress((void**)&su, g_u);

    __nv_bfloat16 *qih, *qil, *kih, *kil, *th, *tl;
    cudaGetSymbolAddress((void**)&qih, g_qih); cudaGetSymbolAddress((void**)&qil, g_qil);
    cudaGetSymbolAddress((void**)&kih, g_kih); cudaGetSymbolAddress((void**)&kil, g_kil);
    cudaGetSymbolAddress((void**)&th, g_th);   cudaGetSymbolAddress((void**)&tl, g_tl);
    __nv_bfloat16 *wqh, *wql, *wkh, *wkl, *wvh, *wvl, *woh, *wol;
    cudaGetSymbolAddress((void**)&wqh, g_wqh); cudaGetSymbolAddress((void**)&wql, g_wql);
    cudaGetSymbolAddress((void**)&wkh, g_wkh); cudaGetSymbolAddress((void**)&wkl, g_wkl);
    cudaGetSymbolAddress((void**)&wvh, g_wvh); cudaGetSymbolAddress((void**)&wvl, g_wvl);
    cudaGetSymbolAddress((void**)&woh, g_woh); cudaGetSymbolAddress((void**)&wol, g_wol);

    const int GEMM_SMEM = 4 * 128 * PSTR * 2;    // 73728 B
    const int ATTN_SMEM = (AG * 4096 + AG * 128) * (int)sizeof(float);
    static int cfg = 0;
    if (!cfg) {
        cudaFuncSetAttribute(hgemm_kernel<0>, cudaFuncAttributeMaxDynamicSharedMemorySize, GEMM_SMEM);
        cudaFuncSetAttribute(hgemm_kernel<1>, cudaFuncAttributeMaxDynamicSharedMemorySize, GEMM_SMEM);
        cudaFuncSetAttribute(attn_kernel, cudaFuncAttributeMaxDynamicSharedMemorySize, ATTN_SMEM);
        cfg = 1;
    }

    const int n4 = ELEMS / 4;
    split_kernel<<<(n4 + 255) / 256, 256>>>((const float4*)Q, (uint2*)qih, (uint2*)qil, n4);
    split_kernel<<<(n4 + 255) / 256, 256>>>((const float4*)K, (uint2*)kih, (uint2*)kil, n4);
    wsplit_kernel<<<DD, DD>>>(Wq, wqh, wql);
    wsplit_kernel<<<DD, DD>>>(Wk, wkh, wkl);
    wsplit_kernel<<<DD, DD>>>(Wv, wvh, wvl);
    wsplit_kernel<<<DD, DD>>>(Wo, woh, wol);

    dim3 gg(ROWS / 128, DD / 128);
    hgemm_kernel<0><<<gg, 256, GEMM_SMEM>>>(qih, qil, wqh, wql, bq, nullptr, sq, lengths);
    hgemm_kernel<0><<<gg, 256, GEMM_SMEM>>>(kih, kil, wkh, wkl, bk, nullptr, sk, lengths);
    hgemm_kernel<0><<<gg, 256, GEMM_SMEM>>>(kih, kil, wvh, wvl, bv, nullptr, sv, lengths);

    attn_kernel<<<dim3(NN / 128, HH, BB), 512, ATTN_SMEM>>>(sq, sk, sv, lengths, so);

    ln_kernel<true><<<ROWS, 256>>>(so, g0, b0, st, th, tl);

    hgemm_kernel<1><<<gg, 256, GEMM_SMEM>>>(th, tl, woh, wol, bo, st, su, nullptr);

    ln_kernel<false><<<ROWS, 256>>>(su, g1, b1, (float*)d_out, nullptr, nullptr);
}

// round 7
// speedup vs baseline: 1.7958x; 1.2282x over previous
#include <cuda_runtime.h>
#include <cuda_bf16.h>
#include <math.h>
#include <stdint.h>

#define BB 8
#define NN 1024
#define DD 256
#define HH 8
#define HD 32
#define ROWS (BB*NN)          // 8192
#define ELEMS (ROWS*DD)       // 2097152

typedef unsigned long long u64;

// -------- scratch (static device globals; no allocation) --------
__device__ float g_q[ELEMS];      // q projection fp32 (residual)
__device__ float g_k[ELEMS];
__device__ float g_v[ELEMS];
__device__ float g_o[ELEMS];      // attention output
__device__ float g_t[ELEMS];      // ln0 out
__device__ float g_u[ELEMS];      // mlp out

__device__ __nv_bfloat16 g_qih[ELEMS];   // input splits (GEMM A operands)
__device__ __nv_bfloat16 g_qil[ELEMS];
__device__ __nv_bfloat16 g_kih[ELEMS];
__device__ __nv_bfloat16 g_kil[ELEMS];
__device__ __nv_bfloat16 g_th[ELEMS];    // ln0 split
__device__ __nv_bfloat16 g_tl[ELEMS];

// attention operand splits (produced by projection epilogues)
__device__ __nv_bfloat16 g_aqh[ELEMS]; __device__ __nv_bfloat16 g_aql[ELEMS];
__device__ __nv_bfloat16 g_akh[ELEMS]; __device__ __nv_bfloat16 g_akl[ELEMS];
__device__ __nv_bfloat16 g_avh[ELEMS]; __device__ __nv_bfloat16 g_avl[ELEMS];

#define WSZ (DD*DD)
__device__ __nv_bfloat16 g_wqh[WSZ]; __device__ __nv_bfloat16 g_wql[WSZ];
__device__ __nv_bfloat16 g_wkh[WSZ]; __device__ __nv_bfloat16 g_wkl[WSZ];
__device__ __nv_bfloat16 g_wvh[WSZ]; __device__ __nv_bfloat16 g_wvl[WSZ];
__device__ __nv_bfloat16 g_woh[WSZ]; __device__ __nv_bfloat16 g_wol[WSZ];

// ---------- helpers ----------
__device__ __forceinline__ void ldmx4(uint32_t* r, uint32_t addr) {
    asm volatile("ldmatrix.sync.aligned.m8n8.x4.shared.b16 {%0,%1,%2,%3}, [%4];"
                 : "=r"(r[0]), "=r"(r[1]), "=r"(r[2]), "=r"(r[3]) : "r"(addr));
}
__device__ __forceinline__ void mma_bf16(float* c, const uint32_t* a, uint32_t b0, uint32_t b1) {
    asm volatile(
        "mma.sync.aligned.m16n8k16.row.col.f32.bf16.bf16.f32 "
        "{%0,%1,%2,%3}, {%4,%5,%6,%7}, {%8,%9}, {%0,%1,%2,%3};"
        : "+f"(c[0]), "+f"(c[1]), "+f"(c[2]), "+f"(c[3])
        : "r"(a[0]), "r"(a[1]), "r"(a[2]), "r"(a[3]), "r"(b0), "r"(b1));
}
// pack: lo half = a, hi half = b  (cvt d,a,b -> hi=a, lo=b per PTX)
__device__ __forceinline__ uint32_t packbf(float lo, float hi) {
    uint32_t r;
    asm("cvt.rn.bf16x2.f32 %0, %1, %2;" : "=r"(r) : "f"(hi), "f"(lo));
    return r;
}
__device__ __forceinline__ float bflo_f(uint32_t p) { return __uint_as_float(p << 16); }
__device__ __forceinline__ float bfhi_f(uint32_t p) { return __uint_as_float(p & 0xFFFF0000u); }

// ================= input split =================
__global__ void __launch_bounds__(256) split_kernel(
    const float4* __restrict__ x, uint2* __restrict__ hi, uint2* __restrict__ lo, int n4)
{
    int i = blockIdx.x * 256 + threadIdx.x;
    if (i >= n4) return;
    float4 v = x[i];
    uint32_t h0 = packbf(v.x, v.y), h1 = packbf(v.z, v.w);
    uint32_t l0 = packbf(v.x - bflo_f(h0), v.y - bfhi_f(h0));
    uint32_t l1 = packbf(v.z - bflo_f(h1), v.w - bfhi_f(h1));
    uint2 hu, lu; hu.x = h0; hu.y = h1; lu.x = l0; lu.y = l1;
    hi[i] = hu; lo[i] = lu;
}

// ================= fused coalesced weight transpose+split (all 4 weights) ============
__global__ void __launch_bounds__(256) wsplit4_kernel(
    const float* __restrict__ Wq, const float* __restrict__ Wk,
    const float* __restrict__ Wv, const float* __restrict__ Wo,
    __nv_bfloat16* __restrict__ qh, __nv_bfloat16* __restrict__ ql,
    __nv_bfloat16* __restrict__ kh, __nv_bfloat16* __restrict__ kl,
    __nv_bfloat16* __restrict__ vh, __nv_bfloat16* __restrict__ vl,
    __nv_bfloat16* __restrict__ oh, __nv_bfloat16* __restrict__ ol)
{
    __shared__ float tile[32][33];
    const float* W; __nv_bfloat16 *th, *tl;
    switch (blockIdx.y) {
        case 0: W = Wq; th = qh; tl = ql; break;
        case 1: W = Wk; th = kh; tl = kl; break;
        case 2: W = Wv; th = vh; tl = vl; break;
        default: W = Wo; th = oh; tl = ol; break;
    }
    const int tx = threadIdx.x & 31, ty = threadIdx.x >> 5;
    const int tR = (blockIdx.x & 7) * 32, tC = (blockIdx.x >> 3) * 32;
    #pragma unroll
    for (int j = 0; j < 4; j++)
        tile[ty + j * 8][tx] = W[(tR + ty + j * 8) * DD + tC + tx];
    __syncthreads();
    #pragma unroll
    for (int j = 0; j < 4; j++) {
        int n = tC + ty + j * 8, k = tR + tx;
        float w = tile[tx][ty + j * 8];
        __nv_bfloat16 h = __float2bfloat16(w);
        th[n * DD + k] = h;
        tl[n * DD + k] = __float2bfloat16(w - __bfloat162float(h));
    }
}

// ================= HMMA GEMM (verified fragments) =================
#define PSTR 72
template<int MODE>
__global__ void __launch_bounds__(256) hgemm_kernel(
    const __nv_bfloat16* __restrict__ Ah_, const __nv_bfloat16* __restrict__ Al_,
    const __nv_bfloat16* __restrict__ Bh_, const __nv_bfloat16* __restrict__ Bl_,
    const float* __restrict__ bias, const float* __restrict__ res,
    float* __restrict__ C, const int* __restrict__ lengths,
    __nv_bfloat16* __restrict__ Ch, __nv_bfloat16* __restrict__ Cl)
{
    extern __shared__ char smc[];
    const int tid = threadIdx.x, wid = tid >> 5, lane = tid & 31;
    const int brow = blockIdx.x * 128, bcol = blockIdx.y * 128;
    const int wm = wid & 1, wn = wid >> 1;

    if (MODE == 0) {
        const int blen = lengths[brow >> 10];
        if ((brow & 1023) >= blen) {
            float4 z = make_float4(0.f, 0.f, 0.f, 0.f);
            uint4 zu = make_uint4(0u, 0u, 0u, 0u);
            #pragma unroll
            for (int i = 0; i < 16; i++) {
                int idx = tid + i * 256;
                int r = idx >> 5, c4 = idx & 31;
                *(float4*)&C[(size_t)(brow + r) * DD + bcol + c4 * 4] = z;
            }
            #pragma unroll
            for (int i = 0; i < 8; i++) {
                int idx = tid + i * 256;          // 128 rows x 16 uint4 (128 bf16)
                int r = idx >> 4, c8 = idx & 15;
                *(uint4*)&Ch[(size_t)(brow + r) * DD + bcol + c8 * 8] = zu;
                *(uint4*)&Cl[(size_t)(brow + r) * DD + bcol + c8 * 8] = zu;
            }
            return;
        }
    }

    __nv_bfloat16* sAh = (__nv_bfloat16*)smc;
    __nv_bfloat16* sAl = sAh + 128 * PSTR;
    __nv_bfloat16* sBh = sAl + 128 * PSTR;
    __nv_bfloat16* sBl = sBh + 128 * PSTR;
    const uint32_t bAh = (uint32_t)__cvta_generic_to_shared(sAh);
    const uint32_t bAl = (uint32_t)__cvta_generic_to_shared(sAl);
    const uint32_t bBh = (uint32_t)__cvta_generic_to_shared(sBh);
    const uint32_t bBl = (uint32_t)__cvta_generic_to_shared(sBl);

    float acc[4][4][4];
    #pragma unroll
    for (int i = 0; i < 4; i++)
        #pragma unroll
        for (int j = 0; j < 4; j++)
            #pragma unroll
            for (int p = 0; p < 4; p++) acc[i][j][p] = 0.f;

    const int aRow = wm * 64 + (lane & 15);
    const int aK   = (lane >> 4) * 8;
    const int bRow = wn * 32 + (lane & 7) + (lane >> 4) * 8;
    const int bK   = ((lane >> 3) & 1) * 8;
    const int ldr = tid >> 3;
    const int ldc = tid & 7;

    for (int ch = 0; ch < 4; ch++) {
        const int kc0 = ch * 64;
        if (ch > 0) __syncthreads();
        #pragma unroll
        for (int i = 0; i < 4; i++) {
            int r = ldr + i * 32;
            size_t ga = (size_t)(brow + r) * DD + kc0 + ldc * 8;
            size_t gb = (size_t)(bcol + r) * DD + kc0 + ldc * 8;
            *(uint4*)&sAh[r * PSTR + ldc * 8] = *(const uint4*)(Ah_ + ga);
            *(uint4*)&sAl[r * PSTR + ldc * 8] = *(const uint4*)(Al_ + ga);
            *(uint4*)&sBh[r * PSTR + ldc * 8] = *(const uint4*)(Bh_ + gb);
            *(uint4*)&sBl[r * PSTR + ldc * 8] = *(const uint4*)(Bl_ + gb);
        }
        __syncthreads();

        #pragma unroll
        for (int ks = 0; ks < 4; ks++) {
            const int kk = ks * 16;
            uint32_t ah[4][4], al[4][4], bh[2][4], bl[2][4];
            #pragma unroll
            for (int mi = 0; mi < 4; mi++) {
                uint32_t off = (uint32_t)((aRow + mi * 16) * PSTR + kk + aK) * 2u;
                ldmx4(ah[mi], bAh + off);
                ldmx4(al[mi], bAl + off);
            }
            #pragma unroll
            for (int n2 = 0; n2 < 2; n2++) {
                uint32_t off = (uint32_t)((bRow + n2 * 16) * PSTR + kk + bK) * 2u;
                ldmx4(bh[n2], bBh + off);
                ldmx4(bl[n2], bBl + off);
            }
            #pragma unroll
            for (int mi = 0; mi < 4; mi++)
                #pragma unroll
                for (int ni = 0; ni < 4; ni++) {
                    uint32_t bh0 = bh[ni >> 1][(ni & 1) * 2], bh1 = bh[ni >> 1][(ni & 1) * 2 + 1];
                    uint32_t bl0 = bl[ni >> 1][(ni & 1) * 2], bl1 = bl[ni >> 1][(ni & 1) * 2 + 1];
                    mma_bf16(acc[mi][ni], ah[mi], bh0, bh1);
                    mma_bf16(acc[mi][ni], ah[mi], bl0, bl1);
                    mma_bf16(acc[mi][ni], al[mi], bh0, bh1);
                }
        }
    }

    const int blen = (MODE == 0) ? lengths[brow >> 10] : 0;
    #pragma unroll
    for (int mi = 0; mi < 4; mi++) {
        int r0 = brow + wm * 64 + mi * 16 + (lane >> 2);
        int r1 = r0 + 8;
        #pragma unroll
        for (int ni = 0; ni < 4; ni++) {
            int col = bcol + wn * 32 + ni * 8 + (lane & 3) * 2;
            float b0 = bias[col], b1 = bias[col + 1];
            float c0 = acc[mi][ni][0] + b0, c1 = acc[mi][ni][1] + b1;
            float c2 = acc[mi][ni][2] + b0, c3 = acc[mi][ni][3] + b1;
            if (MODE == 0) {
                if ((r0 & 1023) >= blen) { c0 = 0.f; c1 = 0.f; }
                if ((r1 & 1023) >= blen) { c2 = 0.f; c3 = 0.f; }
            } else {
                float2 x0 = *(const float2*)&res[(size_t)r0 * DD + col];
                float2 x1 = *(const float2*)&res[(size_t)r1 * DD + col];
                c0 = x0.x + fmaxf(c0, 0.f); c1 = x0.y + fmaxf(c1, 0.f);
                c2 = x1.x + fmaxf(c2, 0.f); c3 = x1.y + fmaxf(c3, 0.f);
            }
            *(float2*)&C[(size_t)r0 * DD + col] = make_float2(c0, c1);
            *(float2*)&C[(size_t)r1 * DD + col] = make_float2(c2, c3);
            if (MODE == 0) {
                uint32_t h0 = packbf(c0, c1), h1 = packbf(c2, c3);
                uint32_t l0 = packbf(c0 - bflo_f(h0), c1 - bfhi_f(h0));
                uint32_t l1 = packbf(c2 - bflo_f(h1), c3 - bfhi_f(h1));
                *(uint32_t*)&Ch[(size_t)r0 * DD + col] = h0;
                *(uint32_t*)&Cl[(size_t)r0 * DD + col] = l0;
                *(uint32_t*)&Ch[(size_t)r1 * DD + col] = h1;
                *(uint32_t*)&Cl[(size_t)r1 * DD + col] = l1;
            }
        }
    }
}

// ================= HMMA attention =================
// block: (qt, h, b); 256 threads = 8 warps, warp w owns q-rows qt*128 + w*16 .. +15.
// S = QK^T bf16x3, exp in-register, P split hi/lo, O += P V bf16x3 (V^T in smem).
#define QSTR 56
#define KSTR 56
#define VSTR 72
#define SM_QH 0
#define SM_QL (SM_QH + 128*QSTR*2)
#define SM_KH (SM_QL + 128*QSTR*2)
#define SM_KL (SM_KH + 64*KSTR*2)
#define SM_VH (SM_KL + 64*KSTR*2)
#define SM_VL (SM_VH + 32*VSTR*2)
#define SM_ATTN (SM_VL + 32*VSTR*2)

__global__ void __launch_bounds__(256) attn_hmma_kernel(
    const __nv_bfloat16* __restrict__ Qh, const __nv_bfloat16* __restrict__ Ql,
    const __nv_bfloat16* __restrict__ Kh, const __nv_bfloat16* __restrict__ Kl,
    const __nv_bfloat16* __restrict__ Vh, const __nv_bfloat16* __restrict__ Vl,
    const float* __restrict__ qres, const int* __restrict__ lengths,
    float* __restrict__ o)
{
    extern __shared__ char smc[];
    const int qt = blockIdx.x, h = blockIdx.y, b = blockIdx.z;
    const int len = lengths[b];
    const int tid = threadIdx.x, w = tid >> 5, lane = tid & 31;

    if (qt * 128 >= len) {
        float4 z = make_float4(0.f, 0.f, 0.f, 0.f);
        #pragma unroll
        for (int i = 0; i < 4; i++) {
            int idx = tid + i * 256;      // 128 rows x 8 float4
            int r = idx >> 3, c4 = idx & 7;
            *(float4*)&o[((size_t)b * NN + qt * 128 + r) * DD + h * HD + c4 * 4] = z;
        }
        return;
    }

    const uint32_t sb = (uint32_t)__cvta_generic_to_shared(smc);

    // ---- load Q tile (128 x 32) hi/lo into smem ----
    {
        const size_t gq = ((size_t)b * NN + qt * 128) * DD + h * HD;
        #pragma unroll
        for (int i = 0; i < 2; i++) {
            int idx = tid + i * 256;      // 0..511: 128 rows x 4 uint4
            int r = idx >> 2, c4 = idx & 3;
            *(uint4*)(smc + SM_QH + (r * QSTR + c4 * 8) * 2) = *(const uint4*)(Qh + gq + (size_t)r * DD + c4 * 8);
            *(uint4*)(smc + SM_QL + (r * QSTR + c4 * 8) * 2) = *(const uint4*)(Ql + gq + (size_t)r * DD + c4 * 8);
        }
    }
    __syncthreads();

    // ---- Q fragments (per warp, fixed) ----
    uint32_t qfh[2][4], qfl[2][4];
    {
        int row = w * 16 + (lane & 15);
        #pragma unroll
        for (int kt = 0; kt < 2; kt++) {
            uint32_t off = (uint32_t)(row * QSTR + kt * 16 + (lane >> 4) * 8) * 2u;
            ldmx4(qfh[kt], sb + SM_QH + off);
            ldmx4(qfl[kt], sb + SM_QL + off);
        }
    }

    float of[4][4];
    #pragma unroll
    for (int i = 0; i < 4; i++)
        #pragma unroll
        for (int p = 0; p < 4; p++) of[i][p] = 0.f;
    float es0 = 0.f, es1 = 0.f;

    const int kRow = (lane & 7) + ((lane >> 4) << 3);
    const int kColHalf = ((lane >> 3) & 1) * 8;

    for (int m0 = 0; m0 < len; m0 += 64) {
        __syncthreads();
        // ---- fill K (64x32 h/l) and V^T (32x64 h/l) ----
        {
            int r = tid >> 2, c4 = tid & 3;
            int row = m0 + r; if (row >= len) row = len - 1;
            size_t gk = ((size_t)b * NN + row) * DD + h * HD + c4 * 8;
            *(uint4*)(smc + SM_KH + (r * KSTR + c4 * 8) * 2) = *(const uint4*)(Kh + gk);
            *(uint4*)(smc + SM_KL + (r * KSTR + c4 * 8) * 2) = *(const uint4*)(Kl + gk);
        }
        {
            int kcol = tid & 63, d0 = (tid >> 6) * 8;
            int row = m0 + kcol; if (row >= len) row = len - 1;
            size_t gv = ((size_t)b * NN + row) * DD + h * HD + d0;
            uint4 vh4 = *(const uint4*)(Vh + gv);
            uint4 vl4 = *(const uint4*)(Vl + gv);
            const uint16_t* ph = (const uint16_t*)&vh4;
            const uint16_t* pl = (const uint16_t*)&vl4;
            #pragma unroll
            for (int j = 0; j < 8; j++) {
                *(uint16_t*)(smc + SM_VH + ((d0 + j) * VSTR + kcol) * 2) = ph[j];
                *(uint16_t*)(smc + SM_VL + ((d0 + j) * VSTR + kcol) * 2) = pl[j];
            }
        }
        __syncthreads();

        // ---- S = Q K^T (bf16x3), 8 n8 tiles ----
        float sf[8][4];
        #pragma unroll
        for (int i = 0; i < 8; i++)
            #pragma unroll
            for (int p = 0; p < 4; p++) sf[i][p] = 0.f;
        #pragma unroll
        for (int kt = 0; kt < 2; kt++) {
            #pragma unroll
            for (int g2 = 0; g2 < 4; g2++) {
                uint32_t off = (uint32_t)((g2 * 16 + kRow) * KSTR + kt * 16 + kColHalf) * 2u;
                uint32_t kbh[4], kbl[4];
                ldmx4(kbh, sb + SM_KH + off);
                ldmx4(kbl, sb + SM_KL + off);
                mma_bf16(sf[g2*2],   qfh[kt], kbh[0], kbh[1]);
                mma_bf16(sf[g2*2],   qfh[kt], kbl[0], kbl[1]);
                mma_bf16(sf[g2*2],   qfl[kt], kbh[0], kbh[1]);
                mma_bf16(sf[g2*2+1], qfh[kt], kbh[2], kbh[3]);
                mma_bf16(sf[g2*2+1], qfh[kt], kbl[2], kbl[3]);
                mma_bf16(sf[g2*2+1], qfl[kt], kbh[2], kbh[3]);
            }
        }

        // ---- exp + split into P fragments ----
        uint32_t ph[8], phb[8], pl[8], plb[8];
        #pragma unroll
        for (int ni = 0; ni < 8; ni++) {
            int k0 = m0 + ni * 8 + ((lane & 3) << 1);
            float e0 = (k0     < len) ? __expf(sf[ni][0] * 0.0625f) : 0.f;
            float e1 = (k0 + 1 < len) ? __expf(sf[ni][1] * 0.0625f) : 0.f;
            float e2 = (k0     < len) ? __expf(sf[ni][2] * 0.0625f) : 0.f;
            float e3 = (k0 + 1 < len) ? __expf(sf[ni][3] * 0.0625f) : 0.f;
            es0 += e0 + e1; es1 += e2 + e3;
            uint32_t h0 = packbf(e0, e1), h1 = packbf(e2, e3);
            ph[ni] = h0; phb[ni] = h1;
            pl[ni]  = packbf(e0 - bflo_f(h0), e1 - bfhi_f(h0));
            plb[ni] = packbf(e2 - bflo_f(h1), e3 - bfhi_f(h1));
        }

        // ---- O += P V (bf16x3), V^T stored [dim 32][key 64] ----
        #pragma unroll
        for (int kt2 = 0; kt2 < 4; kt2++) {
            uint32_t pa_h[4] = { ph[2*kt2], phb[2*kt2], ph[2*kt2+1], phb[2*kt2+1] };
            uint32_t pa_l[4] = { pl[2*kt2], plb[2*kt2], pl[2*kt2+1], plb[2*kt2+1] };
            #pragma unroll
            for (int g2 = 0; g2 < 2; g2++) {
                uint32_t off = (uint32_t)((g2 * 16 + kRow) * VSTR + kt2 * 16 + kColHalf) * 2u;
                uint32_t vbh[4], vbl[4];
                ldmx4(vbh, sb + SM_VH + off);
                ldmx4(vbl, sb + SM_VL + off);
                mma_bf16(of[g2*2],   pa_h, vbh[0], vbh[1]);
                mma_bf16(of[g2*2],   pa_h, vbl[0], vbl[1]);
                mma_bf16(of[g2*2],   pa_l, vbh[0], vbh[1]);
                mma_bf16(of[g2*2+1], pa_h, vbh[2], vbh[3]);
                mma_bf16(of[g2*2+1], pa_h, vbl[2], vbl[3]);
                mma_bf16(of[g2*2+1], pa_l, vbh[2], vbh[3]);
            }
        }
    }

    // ---- finalize: quad-reduce esums, normalize, residual, mask, store ----
    es0 += __shfl_xor_sync(0xFFFFFFFFu, es0, 1);
    es0 += __shfl_xor_sync(0xFFFFFFFFu, es0, 2);
    es1 += __shfl_xor_sync(0xFFFFFFFFu, es1, 1);
    es1 += __shfl_xor_sync(0xFFFFFFFFu, es1, 2);
    const float inv0 = 1.f / (es0 + 1e-15f);
    const float inv1 = 1.f / (es1 + 1e-15f);

    const int n0 = qt * 128 + w * 16 + (lane >> 2);
    const int n1 = n0 + 8;
    const bool a0 = n0 < len, a1 = n1 < len;
    #pragma unroll
    for (int ni = 0; ni < 4; ni++) {
        int col = h * HD + ni * 8 + ((lane & 3) << 1);
        float2 q0 = *(const float2*)&qres[((size_t)b * NN + n0) * DD + col];
        float2 q1 = *(const float2*)&qres[((size_t)b * NN + n1) * DD + col];
        float2 o0, o1;
        o0.x = a0 ? (q0.x + of[ni][0] * inv0) : 0.f;
        o0.y = a0 ? (q0.y + of[ni][1] * inv0) : 0.f;
        o1.x = a1 ? (q1.x + of[ni][2] * inv1) : 0.f;
        o1.y = a1 ? (q1.y + of[ni][3] * inv1) : 0.f;
        *(float2*)&o[((size_t)b * NN + n0) * DD + col] = o0;
        *(float2*)&o[((size_t)b * NN + n1) * DD + col] = o1;
    }
}

// ---------------- LayerNorm (optionally emits bf16 hi/lo split) ----------------
template<bool SPLIT>
__global__ void __launch_bounds__(256) ln_kernel(
    const float* __restrict__ x, const float* __restrict__ g,
    const float* __restrict__ b, float* __restrict__ y,
    __nv_bfloat16* __restrict__ yh, __nv_bfloat16* __restrict__ yl)
{
    const int row = blockIdx.x;
    const int t = threadIdx.x;
    __shared__ float sred[8];

    float v = x[(size_t)row * DD + t];

    float s = v;
    #pragma unroll
    for (int o = 16; o > 0; o >>= 1) s += __shfl_xor_sync(0xFFFFFFFFu, s, o);
    if ((t & 31) == 0) sred[t >> 5] = s;
    __syncthreads();
    float mu = 0.f;
    #pragma unroll
    for (int i = 0; i < 8; i++) mu += sred[i];
    mu *= (1.f / 256.f);

    float d = v - mu;
    float sq = d * d;
    #pragma unroll
    for (int o = 16; o > 0; o >>= 1) sq += __shfl_xor_sync(0xFFFFFFFFu, sq, o);
    __syncthreads();
    if ((t & 31) == 0) sred[t >> 5] = sq;
    __syncthreads();
    float var = 0.f;
    #pragma unroll
    for (int i = 0; i < 8; i++) var += sred[i];
    var *= (1.f / 256.f);

    float r = rsqrtf(var + 1e-5f);
    float out = d * r * g[t] + b[t];
    y[(size_t)row * DD + t] = out;
    if (SPLIT) {
        __nv_bfloat16 hh = __float2bfloat16(out);
        __nv_bfloat16 ll = __float2bfloat16(out - __bfloat162float(hh));
        yh[(size_t)row * DD + t] = hh;
        yl[(size_t)row * DD + t] = ll;
    }
}

// ---------------- launch ----------------
extern "C" void kernel_launch(void* const* d_in, const int* in_sizes, int n_in,
                              void* d_out, int out_size)
{
    const float* Q       = (const float*)d_in[0];
    const float* K       = (const float*)d_in[1];
    const int*   lengths = (const int*)  d_in[2];
    const float* Wq      = (const float*)d_in[3];
    const float* bq      = (const float*)d_in[4];
    const float* Wk      = (const float*)d_in[5];
    const float* bk      = (const float*)d_in[6];
    const float* Wv      = (const float*)d_in[7];
    const float* bv      = (const float*)d_in[8];
    const float* Wo      = (const float*)d_in[9];
    const float* bo      = (const float*)d_in[10];
    const float* g0      = (const float*)d_in[11];
    const float* b0      = (const float*)d_in[12];
    const float* g1      = (const float*)d_in[13];
    const float* b1      = (const float*)d_in[14];

    float *sq, *sk, *sv, *so, *st, *su;
    cudaGetSymbolAddress((void**)&sq, g_q);
    cudaGetSymbolAddress((void**)&sk, g_k);
    cudaGetSymbolAddress((void**)&sv, g_v);
    cudaGetSymbolAddress((void**)&so, g_o);
    cudaGetSymbolAddress((void**)&st, g_t);
    cudaGetSymbolAddress((void**)&su, g_u);

    __nv_bfloat16 *qih, *qil, *kih, *kil, *th, *tl;
    cudaGetSymbolAddress((void**)&qih, g_qih); cudaGetSymbolAddress((void**)&qil, g_qil);
    cudaGetSymbolAddress((void**)&kih, g_kih); cudaGetSymbolAddress((void**)&kil, g_kil);
    cudaGetSymbolAddress((void**)&th, g_th);   cudaGetSymbolAddress((void**)&tl, g_tl);
    __nv_bfloat16 *aqh, *aql, *akh, *akl, *avh, *avl;
    cudaGetSymbolAddress((void**)&aqh, g_aqh); cudaGetSymbolAddress((void**)&aql, g_aql);
    cudaGetSymbolAddress((void**)&akh, g_akh); cudaGetSymbolAddress((void**)&akl, g_akl);
    cudaGetSymbolAddress((void**)&avh, g_avh); cudaGetSymbolAddress((void**)&avl, g_avl);
    __nv_bfloat16 *wqh, *wql, *wkh, *wkl, *wvh, *wvl, *woh, *wol;
    cudaGetSymbolAddress((void**)&wqh, g_wqh); cudaGetSymbolAddress((void**)&wql, g_wql);
    cudaGetSymbolAddress((void**)&wkh, g_wkh); cudaGetSymbolAddress((void**)&wkl, g_wkl);
    cudaGetSymbolAddress((void**)&wvh, g_wvh); cudaGetSymbolAddress((void**)&wvl, g_wvl);
    cudaGetSymbolAddress((void**)&woh, g_woh); cudaGetSymbolAddress((void**)&wol, g_wol);

    const int GEMM_SMEM = 4 * 128 * PSTR * 2;
    static int cfg = 0;
    if (!cfg) {
        cudaFuncSetAttribute(hgemm_kernel<0>, cudaFuncAttributeMaxDynamicSharedMemorySize, GEMM_SMEM);
        cudaFuncSetAttribute(hgemm_kernel<1>, cudaFuncAttributeMaxDynamicSharedMemorySize, GEMM_SMEM);
        cudaFuncSetAttribute(attn_hmma_kernel, cudaFuncAttributeMaxDynamicSharedMemorySize, SM_ATTN);
        cfg = 1;
    }

    const int n4 = ELEMS / 4;
    split_kernel<<<(n4 + 255) / 256, 256>>>((const float4*)Q, (uint2*)qih, (uint2*)qil, n4);
    split_kernel<<<(n4 + 255) / 256, 256>>>((const float4*)K, (uint2*)kih, (uint2*)kil, n4);
    wsplit4_kernel<<<dim3(64, 4), 256>>>(Wq, Wk, Wv, Wo,
        wqh, wql, wkh, wkl, wvh, wvl, woh, wol);

    dim3 gg(ROWS / 128, DD / 128);
    hgemm_kernel<0><<<gg, 256, GEMM_SMEM>>>(qih, qil, wqh, wql, bq, nullptr, sq, lengths, aqh, aql);
    hgemm_kernel<0><<<gg, 256, GEMM_SMEM>>>(kih, kil, wkh, wkl, bk, nullptr, sk, lengths, akh, akl);
    hgemm_kernel<0><<<gg, 256, GEMM_SMEM>>>(kih, kil, wvh, wvl, bv, nullptr, sv, lengths, avh, avl);

    attn_hmma_kernel<<<dim3(NN / 128, HH, BB), 256, SM_ATTN>>>(
        aqh, aql, akh, akl, avh, avl, sq, lengths, so);

    ln_kernel<true><<<ROWS, 256>>>(so, g0, b0, st, th, tl);

    hgemm_kernel<1><<<gg, 256, GEMM_SMEM>>>(th, tl, woh, wol, bo, st, su, lengths, nullptr, nullptr);

    ln_kernel<false><<<ROWS, 256>>>(su, g1, b1, (float*)d_out, nullptr, nullptr);
}

// round 8
// speedup vs baseline: 2.0989x; 1.1688x over previous
#include <cuda_runtime.h>
#include <cuda_bf16.h>
#include <math.h>
#include <stdint.h>

#define BB 8
#define NN 1024
#define DD 256
#define HH 8
#define HD 32
#define ROWS (BB*NN)          // 8192
#define ELEMS (ROWS*DD)       // 2097152

typedef unsigned long long u64;

// -------- scratch (static device globals; no allocation) --------
__device__ float g_q[ELEMS];      // q projection fp32 (residual)
__device__ float g_o[ELEMS];      // attention output
__device__ float g_t[ELEMS];      // ln0 out
__device__ float g_u[ELEMS];      // mlp out

__device__ __nv_bfloat16 g_qih[ELEMS];   // input splits (GEMM A operands)
__device__ __nv_bfloat16 g_qil[ELEMS];
__device__ __nv_bfloat16 g_kih[ELEMS];
__device__ __nv_bfloat16 g_kil[ELEMS];
__device__ __nv_bfloat16 g_th[ELEMS];    // ln0 split
__device__ __nv_bfloat16 g_tl[ELEMS];

// attention operand splits (produced by projection epilogues)
__device__ __nv_bfloat16 g_aqh[ELEMS]; __device__ __nv_bfloat16 g_aql[ELEMS];
__device__ __nv_bfloat16 g_akh[ELEMS]; __device__ __nv_bfloat16 g_akl[ELEMS];
__device__ __nv_bfloat16 g_avh[ELEMS]; __device__ __nv_bfloat16 g_avl[ELEMS];

#define WSZ (DD*DD)
__device__ __nv_bfloat16 g_wqh[WSZ]; __device__ __nv_bfloat16 g_wql[WSZ];
__device__ __nv_bfloat16 g_wkh[WSZ]; __device__ __nv_bfloat16 g_wkl[WSZ];
__device__ __nv_bfloat16 g_wvh[WSZ]; __device__ __nv_bfloat16 g_wvl[WSZ];
__device__ __nv_bfloat16 g_woh[WSZ]; __device__ __nv_bfloat16 g_wol[WSZ];

// ---------- helpers ----------
__device__ __forceinline__ void ldmx4(uint32_t* r, uint32_t addr) {
    asm volatile("ldmatrix.sync.aligned.m8n8.x4.shared.b16 {%0,%1,%2,%3}, [%4];"
                 : "=r"(r[0]), "=r"(r[1]), "=r"(r[2]), "=r"(r[3]) : "r"(addr));
}
__device__ __forceinline__ void mma_bf16(float* c, const uint32_t* a, uint32_t b0, uint32_t b1) {
    asm volatile(
        "mma.sync.aligned.m16n8k16.row.col.f32.bf16.bf16.f32 "
        "{%0,%1,%2,%3}, {%4,%5,%6,%7}, {%8,%9}, {%0,%1,%2,%3};"
        : "+f"(c[0]), "+f"(c[1]), "+f"(c[2]), "+f"(c[3])
        : "r"(a[0]), "r"(a[1]), "r"(a[2]), "r"(a[3]), "r"(b0), "r"(b1));
}
__device__ __forceinline__ uint32_t packbf(float lo, float hi) {
    uint32_t r;
    asm("cvt.rn.bf16x2.f32 %0, %1, %2;" : "=r"(r) : "f"(hi), "f"(lo));
    return r;
}
__device__ __forceinline__ float bflo_f(uint32_t p) { return __uint_as_float(p << 16); }
__device__ __forceinline__ float bfhi_f(uint32_t p) { return __uint_as_float(p & 0xFFFF0000u); }

__device__ __forceinline__ void cpa16(uint32_t saddr, const void* g) {
    asm volatile("cp.async.cg.shared.global [%0], [%1], 16;" :: "r"(saddr), "l"(g));
}
__device__ __forceinline__ void cpa_commit() {
    asm volatile("cp.async.commit_group;" ::: "memory");
}
template<int N>
__device__ __forceinline__ void cpa_wait() {
    asm volatile("cp.async.wait_group %0;" :: "n"(N) : "memory");
}

// ================= input split (Q and K in one launch) =================
__global__ void __launch_bounds__(256) split2_kernel(
    const float4* __restrict__ Q, const float4* __restrict__ K, int n4)
{
    int i = blockIdx.x * 256 + threadIdx.x;
    if (i >= n4) return;
    const float4* x = blockIdx.y ? K : Q;
    uint2* hi = blockIdx.y ? (uint2*)g_kih : (uint2*)g_qih;
    uint2* lo = blockIdx.y ? (uint2*)g_kil : (uint2*)g_qil;
    float4 v = x[i];
    uint32_t h0 = packbf(v.x, v.y), h1 = packbf(v.z, v.w);
    uint32_t l0 = packbf(v.x - bflo_f(h0), v.y - bfhi_f(h0));
    uint32_t l1 = packbf(v.z - bflo_f(h1), v.w - bfhi_f(h1));
    uint2 hu, lu; hu.x = h0; hu.y = h1; lu.x = l0; lu.y = l1;
    hi[i] = hu; lo[i] = lu;
}

// ================= fused coalesced weight transpose+split =================
__global__ void __launch_bounds__(256) wsplit4_kernel(
    const float* __restrict__ Wq, const float* __restrict__ Wk,
    const float* __restrict__ Wv, const float* __restrict__ Wo)
{
    __shared__ float tile[32][33];
    const float* W; __nv_bfloat16 *th, *tl;
    switch (blockIdx.y) {
        case 0: W = Wq; th = g_wqh; tl = g_wql; break;
        case 1: W = Wk; th = g_wkh; tl = g_wkl; break;
        case 2: W = Wv; th = g_wvh; tl = g_wvl; break;
        default: W = Wo; th = g_woh; tl = g_wol; break;
    }
    const int tx = threadIdx.x & 31, ty = threadIdx.x >> 5;
    const int tR = (blockIdx.x & 7) * 32, tC = (blockIdx.x >> 3) * 32;
    #pragma unroll
    for (int j = 0; j < 4; j++)
        tile[ty + j * 8][tx] = W[(tR + ty + j * 8) * DD + tC + tx];
    __syncthreads();
    #pragma unroll
    for (int j = 0; j < 4; j++) {
        int n = tC + ty + j * 8, k = tR + tx;
        float w = tile[tx][ty + j * 8];
        __nv_bfloat16 h = __float2bfloat16(w);
        th[n * DD + k] = h;
        tl[n * DD + k] = __float2bfloat16(w - __bfloat162float(h));
    }
}

// ================= pipelined HMMA GEMM =================
// MODE 0: fused 3 projections (z selects); +bias, mask rows; bf16 split out; fp32 only for z=0.
// MODE 1: MLP: C = res + relu(acc + bias).
#define PSTR 72
#define TILEB (128 * PSTR * 2)     // 18432 B per tile
#define STAGE (4 * TILEB)          // 73728 B per stage
#define GEMM_SMEM2 (2 * STAGE)     // 147456 B

template<int MODE>
__global__ void __launch_bounds__(256) hgemm_kernel(
    const float* __restrict__ bq, const float* __restrict__ bk,
    const float* __restrict__ bv, const float* __restrict__ bo,
    const int* __restrict__ lengths)
{
    extern __shared__ char smc[];
    const int tid = threadIdx.x, wid = tid >> 5, lane = tid & 31;
    const int brow = blockIdx.x * 128, bcol = blockIdx.y * 128;
    const int wm = wid & 1, wn = wid >> 1;

    const __nv_bfloat16 *Ah_, *Al_, *Bh_, *Bl_;
    const float *bias;
    const float *res = nullptr;
    float* C = nullptr;
    __nv_bfloat16 *Ch = nullptr, *Cl = nullptr;
    if (MODE == 0) {
        switch (blockIdx.z) {
            case 0:  Ah_ = g_qih; Al_ = g_qil; Bh_ = g_wqh; Bl_ = g_wql;
                     bias = bq; C = g_q; Ch = g_aqh; Cl = g_aql; break;
            case 1:  Ah_ = g_kih; Al_ = g_kil; Bh_ = g_wkh; Bl_ = g_wkl;
                     bias = bk; Ch = g_akh; Cl = g_akl; break;
            default: Ah_ = g_kih; Al_ = g_kil; Bh_ = g_wvh; Bl_ = g_wvl;
                     bias = bv; Ch = g_avh; Cl = g_avl; break;
        }
    } else {
        Ah_ = g_th; Al_ = g_tl; Bh_ = g_woh; Bl_ = g_wol;
        bias = bo; res = g_t; C = g_u;
    }

    if (MODE == 0) {
        const int blen = lengths[brow >> 10];
        if ((brow & 1023) >= blen) {
            uint4 zu = make_uint4(0u, 0u, 0u, 0u);
            float4 z = make_float4(0.f, 0.f, 0.f, 0.f);
            #pragma unroll
            for (int i = 0; i < 8; i++) {
                int idx = tid + i * 256;           // 128 rows x 16 uint4 (bf16)
                int r = idx >> 4, c8 = idx & 15;
                *(uint4*)&Ch[(size_t)(brow + r) * DD + bcol + c8 * 8] = zu;
                *(uint4*)&Cl[(size_t)(brow + r) * DD + bcol + c8 * 8] = zu;
            }
            if (C) {
                #pragma unroll
                for (int i = 0; i < 16; i++) {
                    int idx = tid + i * 256;
                    int r = idx >> 5, c4 = idx & 31;
                    *(float4*)&C[(size_t)(brow + r) * DD + bcol + c4 * 4] = z;
                }
            }
            return;
        }
    }

    const uint32_t sbu = (uint32_t)__cvta_generic_to_shared(smc);
    const int ldr = tid >> 3;
    const int ldc = tid & 7;

    // async-load one 64-k chunk (4 tiles) into a stage
    auto load_chunk = [&](int ch, int st) {
        const int kc0 = ch * 64;
        const uint32_t s0 = sbu + st * STAGE;
        #pragma unroll
        for (int i = 0; i < 4; i++) {
            int r = ldr + i * 32;
            size_t ga = (size_t)(brow + r) * DD + kc0 + ldc * 8;
            size_t gb = (size_t)(bcol + r) * DD + kc0 + ldc * 8;
            uint32_t so = (uint32_t)(r * PSTR + ldc * 8) * 2u;
            cpa16(s0 + 0 * TILEB + so, Ah_ + ga);
            cpa16(s0 + 1 * TILEB + so, Al_ + ga);
            cpa16(s0 + 2 * TILEB + so, Bh_ + gb);
            cpa16(s0 + 3 * TILEB + so, Bl_ + gb);
        }
    };

    float acc[4][4][4];
    #pragma unroll
    for (int i = 0; i < 4; i++)
        #pragma unroll
        for (int j = 0; j < 4; j++)
            #pragma unroll
            for (int p = 0; p < 4; p++) acc[i][j][p] = 0.f;

    const int aRow = wm * 64 + (lane & 15);
    const int aK   = (lane >> 4) * 8;
    const int bRow = wn * 32 + (lane & 7) + (lane >> 4) * 8;
    const int bK   = ((lane >> 3) & 1) * 8;

    load_chunk(0, 0);
    cpa_commit();

    for (int ch = 0; ch < 4; ch++) {
        if (ch < 3) { load_chunk(ch + 1, (ch + 1) & 1); cpa_commit(); }
        if (ch < 3) cpa_wait<1>(); else cpa_wait<0>();
        __syncthreads();

        const uint32_t stb = sbu + (ch & 1) * STAGE;
        const uint32_t bAh = stb, bAl = stb + TILEB, bBh = stb + 2 * TILEB, bBl = stb + 3 * TILEB;

        #pragma unroll
        for (int ks = 0; ks < 4; ks++) {
            const int kk = ks * 16;
            uint32_t ah[4][4], al[4][4], bh[2][4], bl[2][4];
            #pragma unroll
            for (int mi = 0; mi < 4; mi++) {
                uint32_t off = (uint32_t)((aRow + mi * 16) * PSTR + kk + aK) * 2u;
                ldmx4(ah[mi], bAh + off);
                ldmx4(al[mi], bAl + off);
            }
            #pragma unroll
            for (int n2 = 0; n2 < 2; n2++) {
                uint32_t off = (uint32_t)((bRow + n2 * 16) * PSTR + kk + bK) * 2u;
                ldmx4(bh[n2], bBh + off);
                ldmx4(bl[n2], bBl + off);
            }
            #pragma unroll
            for (int mi = 0; mi < 4; mi++)
                #pragma unroll
                for (int ni = 0; ni < 4; ni++) {
                    uint32_t bh0 = bh[ni >> 1][(ni & 1) * 2], bh1 = bh[ni >> 1][(ni & 1) * 2 + 1];
                    uint32_t bl0 = bl[ni >> 1][(ni & 1) * 2], bl1 = bl[ni >> 1][(ni & 1) * 2 + 1];
                    mma_bf16(acc[mi][ni], ah[mi], bh0, bh1);
                    mma_bf16(acc[mi][ni], ah[mi], bl0, bl1);
                    mma_bf16(acc[mi][ni], al[mi], bh0, bh1);
                }
        }
        __syncthreads();
    }

    const int blen = (MODE == 0) ? lengths[brow >> 10] : 0;
    #pragma unroll
    for (int mi = 0; mi < 4; mi++) {
        int r0 = brow + wm * 64 + mi * 16 + (lane >> 2);
        int r1 = r0 + 8;
        #pragma unroll
        for (int ni = 0; ni < 4; ni++) {
            int col = bcol + wn * 32 + ni * 8 + (lane & 3) * 2;
            float b0 = bias[col], b1 = bias[col + 1];
            float c0 = acc[mi][ni][0] + b0, c1 = acc[mi][ni][1] + b1;
            float c2 = acc[mi][ni][2] + b0, c3 = acc[mi][ni][3] + b1;
            if (MODE == 0) {
                if ((r0 & 1023) >= blen) { c0 = 0.f; c1 = 0.f; }
                if ((r1 & 1023) >= blen) { c2 = 0.f; c3 = 0.f; }
                uint32_t h0 = packbf(c0, c1), h1 = packbf(c2, c3);
                uint32_t l0 = packbf(c0 - bflo_f(h0), c1 - bfhi_f(h0));
                uint32_t l1 = packbf(c2 - bflo_f(h1), c3 - bfhi_f(h1));
                *(uint32_t*)&Ch[(size_t)r0 * DD + col] = h0;
                *(uint32_t*)&Cl[(size_t)r0 * DD + col] = l0;
                *(uint32_t*)&Ch[(size_t)r1 * DD + col] = h1;
                *(uint32_t*)&Cl[(size_t)r1 * DD + col] = l1;
                if (C) {
                    *(float2*)&C[(size_t)r0 * DD + col] = make_float2(c0, c1);
                    *(float2*)&C[(size_t)r1 * DD + col] = make_float2(c2, c3);
                }
            } else {
                float2 x0 = *(const float2*)&res[(size_t)r0 * DD + col];
                float2 x1 = *(const float2*)&res[(size_t)r1 * DD + col];
                c0 = x0.x + fmaxf(c0, 0.f); c1 = x0.y + fmaxf(c1, 0.f);
                c2 = x1.x + fmaxf(c2, 0.f); c3 = x1.y + fmaxf(c3, 0.f);
                *(float2*)&C[(size_t)r0 * DD + col] = make_float2(c0, c1);
                *(float2*)&C[(size_t)r1 * DD + col] = make_float2(c2, c3);
            }
        }
    }
}

// ================= HMMA attention (verified round-7 version) =================
#define QSTR 56
#define KSTR 56
#define VSTR 72
#define SM_QH 0
#define SM_QL (SM_QH + 128*QSTR*2)
#define SM_KH (SM_QL + 128*QSTR*2)
#define SM_KL (SM_KH + 64*KSTR*2)
#define SM_VH (SM_KL + 64*KSTR*2)
#define SM_VL (SM_VH + 32*VSTR*2)
#define SM_ATTN (SM_VL + 32*VSTR*2)

__global__ void __launch_bounds__(256) attn_hmma_kernel(
    const float* __restrict__ qres, const int* __restrict__ lengths,
    float* __restrict__ o)
{
    extern __shared__ char smc[];
    const int qt = blockIdx.x, h = blockIdx.y, b = blockIdx.z;
    const int len = lengths[b];
    const int tid = threadIdx.x, w = tid >> 5, lane = tid & 31;

    if (qt * 128 >= len) {
        float4 z = make_float4(0.f, 0.f, 0.f, 0.f);
        #pragma unroll
        for (int i = 0; i < 4; i++) {
            int idx = tid + i * 256;
            int r = idx >> 3, c4 = idx & 7;
            *(float4*)&o[((size_t)b * NN + qt * 128 + r) * DD + h * HD + c4 * 4] = z;
        }
        return;
    }

    const uint32_t sb = (uint32_t)__cvta_generic_to_shared(smc);

    {
        const size_t gq = ((size_t)b * NN + qt * 128) * DD + h * HD;
        #pragma unroll
        for (int i = 0; i < 2; i++) {
            int idx = tid + i * 256;
            int r = idx >> 2, c4 = idx & 3;
            *(uint4*)(smc + SM_QH + (r * QSTR + c4 * 8) * 2) = *(const uint4*)(g_aqh + gq + (size_t)r * DD + c4 * 8);
            *(uint4*)(smc + SM_QL + (r * QSTR + c4 * 8) * 2) = *(const uint4*)(g_aql + gq + (size_t)r * DD + c4 * 8);
        }
    }
    __syncthreads();

    uint32_t qfh[2][4], qfl[2][4];
    {
        int row = w * 16 + (lane & 15);
        #pragma unroll
        for (int kt = 0; kt < 2; kt++) {
            uint32_t off = (uint32_t)(row * QSTR + kt * 16 + (lane >> 4) * 8) * 2u;
            ldmx4(qfh[kt], sb + SM_QH + off);
            ldmx4(qfl[kt], sb + SM_QL + off);
        }
    }

    float of[4][4];
    #pragma unroll
    for (int i = 0; i < 4; i++)
        #pragma unroll
        for (int p = 0; p < 4; p++) of[i][p] = 0.f;
    float es0 = 0.f, es1 = 0.f;

    const int kRow = (lane & 7) + ((lane >> 4) << 3);
    const int kColHalf = ((lane >> 3) & 1) * 8;

    for (int m0 = 0; m0 < len; m0 += 64) {
        __syncthreads();
        {
            int r = tid >> 2, c4 = tid & 3;
            int row = m0 + r; if (row >= len) row = len - 1;
            size_t gk = ((size_t)b * NN + row) * DD + h * HD + c4 * 8;
            *(uint4*)(smc + SM_KH + (r * KSTR + c4 * 8) * 2) = *(const uint4*)(g_akh + gk);
            *(uint4*)(smc + SM_KL + (r * KSTR + c4 * 8) * 2) = *(const uint4*)(g_akl + gk);
        }
        {
            int kcol = tid & 63, d0 = (tid >> 6) * 8;
            int row = m0 + kcol; if (row >= len) row = len - 1;
            size_t gv = ((size_t)b * NN + row) * DD + h * HD + d0;
            uint4 vh4 = *(const uint4*)(g_avh + gv);
            uint4 vl4 = *(const uint4*)(g_avl + gv);
            const uint16_t* ph = (const uint16_t*)&vh4;
            const uint16_t* pl = (const uint16_t*)&vl4;
            #pragma unroll
            for (int j = 0; j < 8; j++) {
                *(uint16_t*)(smc + SM_VH + ((d0 + j) * VSTR + kcol) * 2) = ph[j];
                *(uint16_t*)(smc + SM_VL + ((d0 + j) * VSTR + kcol) * 2) = pl[j];
            }
        }
        __syncthreads();

        float sf[8][4];
        #pragma unroll
        for (int i = 0; i < 8; i++)
            #pragma unroll
            for (int p = 0; p < 4; p++) sf[i][p] = 0.f;
        #pragma unroll
        for (int kt = 0; kt < 2; kt++) {
            #pragma unroll
            for (int g2 = 0; g2 < 4; g2++) {
                uint32_t off = (uint32_t)((g2 * 16 + kRow) * KSTR + kt * 16 + kColHalf) * 2u;
                uint32_t kbh[4], kbl[4];
                ldmx4(kbh, sb + SM_KH + off);
                ldmx4(kbl, sb + SM_KL + off);
                mma_bf16(sf[g2*2],   qfh[kt], kbh[0], kbh[1]);
                mma_bf16(sf[g2*2],   qfh[kt], kbl[0], kbl[1]);
                mma_bf16(sf[g2*2],   qfl[kt], kbh[0], kbh[1]);
                mma_bf16(sf[g2*2+1], qfh[kt], kbh[2], kbh[3]);
                mma_bf16(sf[g2*2+1], qfh[kt], kbl[2], kbl[3]);
                mma_bf16(sf[g2*2+1], qfl[kt], kbh[2], kbh[3]);
            }
        }

        uint32_t ph[8], phb[8], pl[8], plb[8];
        #pragma unroll
        for (int ni = 0; ni < 8; ni++) {
            int k0 = m0 + ni * 8 + ((lane & 3) << 1);
            float e0 = (k0     < len) ? __expf(sf[ni][0] * 0.0625f) : 0.f;
            float e1 = (k0 + 1 < len) ? __expf(sf[ni][1] * 0.0625f) : 0.f;
            float e2 = (k0     < len) ? __expf(sf[ni][2] * 0.0625f) : 0.f;
            float e3 = (k0 + 1 < len) ? __expf(sf[ni][3] * 0.0625f) : 0.f;
            es0 += e0 + e1; es1 += e2 + e3;
            uint32_t h0 = packbf(e0, e1), h1 = packbf(e2, e3);
            ph[ni] = h0; phb[ni] = h1;
            pl[ni]  = packbf(e0 - bflo_f(h0), e1 - bfhi_f(h0));
            plb[ni] = packbf(e2 - bflo_f(h1), e3 - bfhi_f(h1));
        }

        #pragma unroll
        for (int kt2 = 0; kt2 < 4; kt2++) {
            uint32_t pa_h[4] = { ph[2*kt2], phb[2*kt2], ph[2*kt2+1], phb[2*kt2+1] };
            uint32_t pa_l[4] = { pl[2*kt2], plb[2*kt2], pl[2*kt2+1], plb[2*kt2+1] };
            #pragma unroll
            for (int g2 = 0; g2 < 2; g2++) {
                uint32_t off = (uint32_t)((g2 * 16 + kRow) * VSTR + kt2 * 16 + kColHalf) * 2u;
                uint32_t vbh[4], vbl[4];
                ldmx4(vbh, sb + SM_VH + off);
                ldmx4(vbl, sb + SM_VL + off);
                mma_bf16(of[g2*2],   pa_h, vbh[0], vbh[1]);
                mma_bf16(of[g2*2],   pa_h, vbl[0], vbl[1]);
                mma_bf16(of[g2*2],   pa_l, vbh[0], vbh[1]);
                mma_bf16(of[g2*2+1], pa_h, vbh[2], vbh[3]);
                mma_bf16(of[g2*2+1], pa_h, vbl[2], vbl[3]);
                mma_bf16(of[g2*2+1], pa_l, vbh[2], vbh[3]);
            }
        }
    }

    es0 += __shfl_xor_sync(0xFFFFFFFFu, es0, 1);
    es0 += __shfl_xor_sync(0xFFFFFFFFu, es0, 2);
    es1 += __shfl_xor_sync(0xFFFFFFFFu, es1, 1);
    es1 += __shfl_xor_sync(0xFFFFFFFFu, es1, 2);
    const float inv0 = 1.f / (es0 + 1e-15f);
    const float inv1 = 1.f / (es1 + 1e-15f);

    const int n0 = qt * 128 + w * 16 + (lane >> 2);
    const int n1 = n0 + 8;
    const bool a0 = n0 < len, a1 = n1 < len;
    #pragma unroll
    for (int ni = 0; ni < 4; ni++) {
        int col = h * HD + ni * 8 + ((lane & 3) << 1);
        float2 q0 = *(const float2*)&qres[((size_t)b * NN + n0) * DD + col];
        float2 q1 = *(const float2*)&qres[((size_t)b * NN + n1) * DD + col];
        float2 o0, o1;
        o0.x = a0 ? (q0.x + of[ni][0] * inv0) : 0.f;
        o0.y = a0 ? (q0.y + of[ni][1] * inv0) : 0.f;
        o1.x = a1 ? (q1.x + of[ni][2] * inv1) : 0.f;
        o1.y = a1 ? (q1.y + of[ni][3] * inv1) : 0.f;
        *(float2*)&o[((size_t)b * NN + n0) * DD + col] = o0;
        *(float2*)&o[((size_t)b * NN + n1) * DD + col] = o1;
    }
}

// ---------------- LayerNorm (optionally emits bf16 hi/lo split) ----------------
template<bool SPLIT>
__global__ void __launch_bounds__(256) ln_kernel(
    const float* __restrict__ x, const float* __restrict__ g,
    const float* __restrict__ b, float* __restrict__ y,
    __nv_bfloat16* __restrict__ yh, __nv_bfloat16* __restrict__ yl)
{
    const int row = blockIdx.x;
    const int t = threadIdx.x;
    __shared__ float sred[8];

    float v = x[(size_t)row * DD + t];

    float s = v;
    #pragma unroll
    for (int o = 16; o > 0; o >>= 1) s += __shfl_xor_sync(0xFFFFFFFFu, s, o);
    if ((t & 31) == 0) sred[t >> 5] = s;
    __syncthreads();
    float mu = 0.f;
    #pragma unroll
    for (int i = 0; i < 8; i++) mu += sred[i];
    mu *= (1.f / 256.f);

    float d = v - mu;
    float sq = d * d;
    #pragma unroll
    for (int o = 16; o > 0; o >>= 1) sq += __shfl_xor_sync(0xFFFFFFFFu, sq, o);
    __syncthreads();
    if ((t & 31) == 0) sred[t >> 5] = sq;
    __syncthreads();
    float var = 0.f;
    #pragma unroll
    for (int i = 0; i < 8; i++) var += sred[i];
    var *= (1.f / 256.f);

    float r = rsqrtf(var + 1e-5f);
    float out = d * r * g[t] + b[t];
    y[(size_t)row * DD + t] = out;
    if (SPLIT) {
        __nv_bfloat16 hh = __float2bfloat16(out);
        __nv_bfloat16 ll = __float2bfloat16(out - __bfloat162float(hh));
        yh[(size_t)row * DD + t] = hh;
        yl[(size_t)row * DD + t] = ll;
    }
}

// ---------------- launch ----------------
extern "C" void kernel_launch(void* const* d_in, const int* in_sizes, int n_in,
                              void* d_out, int out_size)
{
    const float* Q       = (const float*)d_in[0];
    const float* K       = (const float*)d_in[1];
    const int*   lengths = (const int*)  d_in[2];
    const float* Wq      = (const float*)d_in[3];
    const float* bq      = (const float*)d_in[4];
    const float* Wk      = (const float*)d_in[5];
    const float* bk      = (const float*)d_in[6];
    const float* Wv      = (const float*)d_in[7];
    const float* bv      = (const float*)d_in[8];
    const float* Wo      = (const float*)d_in[9];
    const float* bo      = (const float*)d_in[10];
    const float* g0      = (const float*)d_in[11];
    const float* b0      = (const float*)d_in[12];
    const float* g1      = (const float*)d_in[13];
    const float* b1      = (const float*)d_in[14];

    float *sq, *so, *st, *su;
    cudaGetSymbolAddress((void**)&sq, g_q);
    cudaGetSymbolAddress((void**)&so, g_o);
    cudaGetSymbolAddress((void**)&st, g_t);
    cudaGetSymbolAddress((void**)&su, g_u);
    __nv_bfloat16 *th, *tl;
    cudaGetSymbolAddress((void**)&th, g_th);
    cudaGetSymbolAddress((void**)&tl, g_tl);

    static int cfg = 0;
    if (!cfg) {
        cudaFuncSetAttribute(hgemm_kernel<0>, cudaFuncAttributeMaxDynamicSharedMemorySize, GEMM_SMEM2);
        cudaFuncSetAttribute(hgemm_kernel<1>, cudaFuncAttributeMaxDynamicSharedMemorySize, GEMM_SMEM2);
        cudaFuncSetAttribute(attn_hmma_kernel, cudaFuncAttributeMaxDynamicSharedMemorySize, SM_ATTN);
        cfg = 1;
    }

    const int n4 = ELEMS / 4;
    split2_kernel<<<dim3((n4 + 255) / 256, 2), 256>>>((const float4*)Q, (const float4*)K, n4);
    wsplit4_kernel<<<dim3(64, 4), 256>>>(Wq, Wk, Wv, Wo);

    hgemm_kernel<0><<<dim3(ROWS / 128, DD / 128, 3), 256, GEMM_SMEM2>>>(bq, bk, bv, bo, lengths);

    attn_hmma_kernel<<<dim3(NN / 128, HH, BB), 256, SM_ATTN>>>(sq, lengths, so);

    ln_kernel<true><<<ROWS, 256>>>(so, g0, b0, st, th, tl);

    hgemm_kernel<1><<<dim3(ROWS / 128, DD / 128, 1), 256, GEMM_SMEM2>>>(bq, bk, bv, bo, lengths);

    ln_kernel<false><<<ROWS, 256>>>(su, g1, b1, (float*)d_out, nullptr, nullptr);
}

// round 9
// speedup vs baseline: 2.2509x; 1.0724x over previous
#include <cuda_runtime.h>
#include <cuda_bf16.h>
#include <math.h>
#include <stdint.h>

#define BB 8
#define NN 1024
#define DD 256
#define HH 8
#define HD 32
#define ROWS (BB*NN)          // 8192
#define ELEMS (ROWS*DD)       // 2097152

typedef unsigned long long u64;

// -------- scratch (static device globals; no allocation) --------
__device__ float g_q[ELEMS];      // q projection fp32 (residual)
__device__ float g_o[ELEMS];      // attention output
__device__ float g_t[ELEMS];      // ln0 out
__device__ float g_u[ELEMS];      // mlp out

__device__ __nv_bfloat16 g_qih[ELEMS];   // input splits (GEMM A operands)
__device__ __nv_bfloat16 g_qil[ELEMS];
__device__ __nv_bfloat16 g_kih[ELEMS];
__device__ __nv_bfloat16 g_kil[ELEMS];
__device__ __nv_bfloat16 g_th[ELEMS];    // ln0 split
__device__ __nv_bfloat16 g_tl[ELEMS];

// attention operand splits (produced by projection epilogues)
__device__ __nv_bfloat16 g_aqh[ELEMS]; __device__ __nv_bfloat16 g_aql[ELEMS];
__device__ __nv_bfloat16 g_akh[ELEMS]; __device__ __nv_bfloat16 g_akl[ELEMS];
__device__ __nv_bfloat16 g_avh[ELEMS]; __device__ __nv_bfloat16 g_avl[ELEMS];

#define WSZ (DD*DD)
__device__ __nv_bfloat16 g_wqh[WSZ]; __device__ __nv_bfloat16 g_wql[WSZ];
__device__ __nv_bfloat16 g_wkh[WSZ]; __device__ __nv_bfloat16 g_wkl[WSZ];
__device__ __nv_bfloat16 g_wvh[WSZ]; __device__ __nv_bfloat16 g_wvl[WSZ];
__device__ __nv_bfloat16 g_woh[WSZ]; __device__ __nv_bfloat16 g_wol[WSZ];

// ---------- helpers ----------
__device__ __forceinline__ void ldmx4(uint32_t* r, uint32_t addr) {
    asm volatile("ldmatrix.sync.aligned.m8n8.x4.shared.b16 {%0,%1,%2,%3}, [%4];"
                 : "=r"(r[0]), "=r"(r[1]), "=r"(r[2]), "=r"(r[3]) : "r"(addr));
}
__device__ __forceinline__ void ldmx4t(uint32_t* r, uint32_t addr) {
    asm volatile("ldmatrix.sync.aligned.m8n8.x4.trans.shared.b16 {%0,%1,%2,%3}, [%4];"
                 : "=r"(r[0]), "=r"(r[1]), "=r"(r[2]), "=r"(r[3]) : "r"(addr));
}
__device__ __forceinline__ void mma_bf16(float* c, const uint32_t* a, uint32_t b0, uint32_t b1) {
    asm volatile(
        "mma.sync.aligned.m16n8k16.row.col.f32.bf16.bf16.f32 "
        "{%0,%1,%2,%3}, {%4,%5,%6,%7}, {%8,%9}, {%0,%1,%2,%3};"
        : "+f"(c[0]), "+f"(c[1]), "+f"(c[2]), "+f"(c[3])
        : "r"(a[0]), "r"(a[1]), "r"(a[2]), "r"(a[3]), "r"(b0), "r"(b1));
}
__device__ __forceinline__ uint32_t packbf(float lo, float hi) {
    uint32_t r;
    asm("cvt.rn.bf16x2.f32 %0, %1, %2;" : "=r"(r) : "f"(hi), "f"(lo));
    return r;
}
__device__ __forceinline__ float bflo_f(uint32_t p) { return __uint_as_float(p << 16); }
__device__ __forceinline__ float bfhi_f(uint32_t p) { return __uint_as_float(p & 0xFFFF0000u); }

__device__ __forceinline__ void cpa16(uint32_t saddr, const void* g) {
    asm volatile("cp.async.cg.shared.global [%0], [%1], 16;" :: "r"(saddr), "l"(g));
}
__device__ __forceinline__ void cpa_commit() {
    asm volatile("cp.async.commit_group;" ::: "memory");
}
template<int N>
__device__ __forceinline__ void cpa_wait() {
    asm volatile("cp.async.wait_group %0;" :: "n"(N) : "memory");
}

// ================= input split (Q and K in one launch) =================
__global__ void __launch_bounds__(256) split2_kernel(
    const float4* __restrict__ Q, const float4* __restrict__ K, int n4)
{
    int i = blockIdx.x * 256 + threadIdx.x;
    if (i >= n4) return;
    const float4* x = blockIdx.y ? K : Q;
    uint2* hi = blockIdx.y ? (uint2*)g_kih : (uint2*)g_qih;
    uint2* lo = blockIdx.y ? (uint2*)g_kil : (uint2*)g_qil;
    float4 v = x[i];
    uint32_t h0 = packbf(v.x, v.y), h1 = packbf(v.z, v.w);
    uint32_t l0 = packbf(v.x - bflo_f(h0), v.y - bfhi_f(h0));
    uint32_t l1 = packbf(v.z - bflo_f(h1), v.w - bfhi_f(h1));
    uint2 hu, lu; hu.x = h0; hu.y = h1; lu.x = l0; lu.y = l1;
    hi[i] = hu; lo[i] = lu;
}

// ================= fused coalesced weight transpose+split =================
__global__ void __launch_bounds__(256) wsplit4_kernel(
    const float* __restrict__ Wq, const float* __restrict__ Wk,
    const float* __restrict__ Wv, const float* __restrict__ Wo)
{
    __shared__ float tile[32][33];
    const float* W; __nv_bfloat16 *th, *tl;
    switch (blockIdx.y) {
        case 0: W = Wq; th = g_wqh; tl = g_wql; break;
        case 1: W = Wk; th = g_wkh; tl = g_wkl; break;
        case 2: W = Wv; th = g_wvh; tl = g_wvl; break;
        default: W = Wo; th = g_woh; tl = g_wol; break;
    }
    const int tx = threadIdx.x & 31, ty = threadIdx.x >> 5;
    const int tR = (blockIdx.x & 7) * 32, tC = (blockIdx.x >> 3) * 32;
    #pragma unroll
    for (int j = 0; j < 4; j++)
        tile[ty + j * 8][tx] = W[(tR + ty + j * 8) * DD + tC + tx];
    __syncthreads();
    #pragma unroll
    for (int j = 0; j < 4; j++) {
        int n = tC + ty + j * 8, k = tR + tx;
        float w = tile[tx][ty + j * 8];
        __nv_bfloat16 h = __float2bfloat16(w);
        th[n * DD + k] = h;
        tl[n * DD + k] = __float2bfloat16(w - __bfloat162float(h));
    }
}

// ================= pipelined HMMA GEMM (round-8 verified) =================
#define PSTR 72
#define TILEB (128 * PSTR * 2)
#define STAGE (4 * TILEB)
#define GEMM_SMEM2 (2 * STAGE)

template<int MODE>
__global__ void __launch_bounds__(256) hgemm_kernel(
    const float* __restrict__ bq, const float* __restrict__ bk,
    const float* __restrict__ bv, const float* __restrict__ bo,
    const int* __restrict__ lengths)
{
    extern __shared__ char smc[];
    const int tid = threadIdx.x, wid = tid >> 5, lane = tid & 31;
    const int brow = blockIdx.x * 128, bcol = blockIdx.y * 128;
    const int wm = wid & 1, wn = wid >> 1;

    const __nv_bfloat16 *Ah_, *Al_, *Bh_, *Bl_;
    const float *bias;
    const float *res = nullptr;
    float* C = nullptr;
    __nv_bfloat16 *Ch = nullptr, *Cl = nullptr;
    if (MODE == 0) {
        switch (blockIdx.z) {
            case 0:  Ah_ = g_qih; Al_ = g_qil; Bh_ = g_wqh; Bl_ = g_wql;
                     bias = bq; C = g_q; Ch = g_aqh; Cl = g_aql; break;
            case 1:  Ah_ = g_kih; Al_ = g_kil; Bh_ = g_wkh; Bl_ = g_wkl;
                     bias = bk; Ch = g_akh; Cl = g_akl; break;
            default: Ah_ = g_kih; Al_ = g_kil; Bh_ = g_wvh; Bl_ = g_wvl;
                     bias = bv; Ch = g_avh; Cl = g_avl; break;
        }
    } else {
        Ah_ = g_th; Al_ = g_tl; Bh_ = g_woh; Bl_ = g_wol;
        bias = bo; res = g_t; C = g_u;
    }

    if (MODE == 0) {
        const int blen = lengths[brow >> 10];
        if ((brow & 1023) >= blen) {
            uint4 zu = make_uint4(0u, 0u, 0u, 0u);
            float4 z = make_float4(0.f, 0.f, 0.f, 0.f);
            #pragma unroll
            for (int i = 0; i < 8; i++) {
                int idx = tid + i * 256;
                int r = idx >> 4, c8 = idx & 15;
                *(uint4*)&Ch[(size_t)(brow + r) * DD + bcol + c8 * 8] = zu;
                *(uint4*)&Cl[(size_t)(brow + r) * DD + bcol + c8 * 8] = zu;
            }
            if (C) {
                #pragma unroll
                for (int i = 0; i < 16; i++) {
                    int idx = tid + i * 256;
                    int r = idx >> 5, c4 = idx & 31;
                    *(float4*)&C[(size_t)(brow + r) * DD + bcol + c4 * 4] = z;
                }
            }
            return;
        }
    }

    const uint32_t sbu = (uint32_t)__cvta_generic_to_shared(smc);
    const int ldr = tid >> 3;
    const int ldc = tid & 7;

    auto load_chunk = [&](int ch, int st) {
        const int kc0 = ch * 64;
        const uint32_t s0 = sbu + st * STAGE;
        #pragma unroll
        for (int i = 0; i < 4; i++) {
            int r = ldr + i * 32;
            size_t ga = (size_t)(brow + r) * DD + kc0 + ldc * 8;
            size_t gb = (size_t)(bcol + r) * DD + kc0 + ldc * 8;
            uint32_t so = (uint32_t)(r * PSTR + ldc * 8) * 2u;
            cpa16(s0 + 0 * TILEB + so, Ah_ + ga);
            cpa16(s0 + 1 * TILEB + so, Al_ + ga);
            cpa16(s0 + 2 * TILEB + so, Bh_ + gb);
            cpa16(s0 + 3 * TILEB + so, Bl_ + gb);
        }
    };

    float acc[4][4][4];
    #pragma unroll
    for (int i = 0; i < 4; i++)
        #pragma unroll
        for (int j = 0; j < 4; j++)
            #pragma unroll
            for (int p = 0; p < 4; p++) acc[i][j][p] = 0.f;

    const int aRow = wm * 64 + (lane & 15);
    const int aK   = (lane >> 4) * 8;
    const int bRow = wn * 32 + (lane & 7) + (lane >> 4) * 8;
    const int bK   = ((lane >> 3) & 1) * 8;

    load_chunk(0, 0);
    cpa_commit();

    for (int ch = 0; ch < 4; ch++) {
        if (ch < 3) { load_chunk(ch + 1, (ch + 1) & 1); cpa_commit(); }
        if (ch < 3) cpa_wait<1>(); else cpa_wait<0>();
        __syncthreads();

        const uint32_t stb = sbu + (ch & 1) * STAGE;
        const uint32_t bAh = stb, bAl = stb + TILEB, bBh = stb + 2 * TILEB, bBl = stb + 3 * TILEB;

        #pragma unroll
        for (int ks = 0; ks < 4; ks++) {
            const int kk = ks * 16;
            uint32_t ah[4][4], al[4][4], bh[2][4], bl[2][4];
            #pragma unroll
            for (int mi = 0; mi < 4; mi++) {
                uint32_t off = (uint32_t)((aRow + mi * 16) * PSTR + kk + aK) * 2u;
                ldmx4(ah[mi], bAh + off);
                ldmx4(al[mi], bAl + off);
            }
            #pragma unroll
            for (int n2 = 0; n2 < 2; n2++) {
                uint32_t off = (uint32_t)((bRow + n2 * 16) * PSTR + kk + bK) * 2u;
                ldmx4(bh[n2], bBh + off);
                ldmx4(bl[n2], bBl + off);
            }
            #pragma unroll
            for (int mi = 0; mi < 4; mi++)
                #pragma unroll
                for (int ni = 0; ni < 4; ni++) {
                    uint32_t bh0 = bh[ni >> 1][(ni & 1) * 2], bh1 = bh[ni >> 1][(ni & 1) * 2 + 1];
                    uint32_t bl0 = bl[ni >> 1][(ni & 1) * 2], bl1 = bl[ni >> 1][(ni & 1) * 2 + 1];
                    mma_bf16(acc[mi][ni], ah[mi], bh0, bh1);
                    mma_bf16(acc[mi][ni], ah[mi], bl0, bl1);
                    mma_bf16(acc[mi][ni], al[mi], bh0, bh1);
                }
        }
        __syncthreads();
    }

    const int blen = (MODE == 0) ? lengths[brow >> 10] : 0;
    #pragma unroll
    for (int mi = 0; mi < 4; mi++) {
        int r0 = brow + wm * 64 + mi * 16 + (lane >> 2);
        int r1 = r0 + 8;
        #pragma unroll
        for (int ni = 0; ni < 4; ni++) {
            int col = bcol + wn * 32 + ni * 8 + (lane & 3) * 2;
            float b0 = bias[col], b1 = bias[col + 1];
            float c0 = acc[mi][ni][0] + b0, c1 = acc[mi][ni][1] + b1;
            float c2 = acc[mi][ni][2] + b0, c3 = acc[mi][ni][3] + b1;
            if (MODE == 0) {
                if ((r0 & 1023) >= blen) { c0 = 0.f; c1 = 0.f; }
                if ((r1 & 1023) >= blen) { c2 = 0.f; c3 = 0.f; }
                uint32_t h0 = packbf(c0, c1), h1 = packbf(c2, c3);
                uint32_t l0 = packbf(c0 - bflo_f(h0), c1 - bfhi_f(h0));
                uint32_t l1 = packbf(c2 - bflo_f(h1), c3 - bfhi_f(h1));
                *(uint32_t*)&Ch[(size_t)r0 * DD + col] = h0;
                *(uint32_t*)&Cl[(size_t)r0 * DD + col] = l0;
                *(uint32_t*)&Ch[(size_t)r1 * DD + col] = h1;
                *(uint32_t*)&Cl[(size_t)r1 * DD + col] = l1;
                if (C) {
                    *(float2*)&C[(size_t)r0 * DD + col] = make_float2(c0, c1);
                    *(float2*)&C[(size_t)r1 * DD + col] = make_float2(c2, c3);
                }
            } else {
                float2 x0 = *(const float2*)&res[(size_t)r0 * DD + col];
                float2 x1 = *(const float2*)&res[(size_t)r1 * DD + col];
                c0 = x0.x + fmaxf(c0, 0.f); c1 = x0.y + fmaxf(c1, 0.f);
                c2 = x1.x + fmaxf(c2, 0.f); c3 = x1.y + fmaxf(c3, 0.f);
                *(float2*)&C[(size_t)r0 * DD + col] = make_float2(c0, c1);
                *(float2*)&C[(size_t)r1 * DD + col] = make_float2(c2, c3);
            }
        }
    }
}

// ================= HMMA attention: trans-ldmatrix V + cp.async double buffer ============
#define QSTR 56
#define KSTR 56
#define VSTR2 40
#define SM_QH 0
#define SM_QL (SM_QH + 128*QSTR*2)      // 14336
#define SM_ST0 (SM_QL + 128*QSTR*2)     // 28672
#define KBYTES (64*KSTR*2)              // 7168
#define VBYTES (64*VSTR2*2)             // 5120
#define STAGEA (2*KBYTES + 2*VBYTES)    // 24576
#define SM_ATTN2 (SM_ST0 + 2*STAGEA)    // 77824

__global__ void __launch_bounds__(256) attn_hmma_kernel(
    const float* __restrict__ qres, const int* __restrict__ lengths,
    float* __restrict__ o)
{
    extern __shared__ char smc[];
    const int qt = blockIdx.x, h = blockIdx.y, b = blockIdx.z;
    const int len = lengths[b];
    const int tid = threadIdx.x, w = tid >> 5, lane = tid & 31;

    if (qt * 128 >= len) {
        float4 z = make_float4(0.f, 0.f, 0.f, 0.f);
        #pragma unroll
        for (int i = 0; i < 4; i++) {
            int idx = tid + i * 256;
            int r = idx >> 3, c4 = idx & 7;
            *(float4*)&o[((size_t)b * NN + qt * 128 + r) * DD + h * HD + c4 * 4] = z;
        }
        return;
    }

    const uint32_t sb = (uint32_t)__cvta_generic_to_shared(smc);

    // cp.async one 64-key K+V tile (hi/lo) into stage st
    const int ldr = tid >> 2, ldc4 = tid & 3;
    auto load_tile = [&](int m0, int st) {
        int row = m0 + ldr; if (row >= len) row = len - 1;
        size_t g = ((size_t)b * NN + row) * DD + h * HD + ldc4 * 8;
        uint32_t s0 = sb + SM_ST0 + st * STAGEA;
        cpa16(s0 + (uint32_t)(ldr * KSTR + ldc4 * 8) * 2u,           g_akh + g);
        cpa16(s0 + KBYTES + (uint32_t)(ldr * KSTR + ldc4 * 8) * 2u,  g_akl + g);
        cpa16(s0 + 2*KBYTES + (uint32_t)(ldr * VSTR2 + ldc4 * 8) * 2u,          g_avh + g);
        cpa16(s0 + 2*KBYTES + VBYTES + (uint32_t)(ldr * VSTR2 + ldc4 * 8) * 2u, g_avl + g);
    };

    // prefetch tile 0 while Q is stored
    load_tile(0, 0);
    cpa_commit();

    {   // Q tile (128 x 32) hi/lo
        const size_t gq = ((size_t)b * NN + qt * 128) * DD + h * HD;
        #pragma unroll
        for (int i = 0; i < 2; i++) {
            int idx = tid + i * 256;
            int r = idx >> 2, c4 = idx & 3;
            *(uint4*)(smc + SM_QH + (r * QSTR + c4 * 8) * 2) = *(const uint4*)(g_aqh + gq + (size_t)r * DD + c4 * 8);
            *(uint4*)(smc + SM_QL + (r * QSTR + c4 * 8) * 2) = *(const uint4*)(g_aql + gq + (size_t)r * DD + c4 * 8);
        }
    }
    __syncthreads();

    uint32_t qfh[2][4], qfl[2][4];
    {
        int row = w * 16 + (lane & 15);
        #pragma unroll
        for (int kt = 0; kt < 2; kt++) {
            uint32_t off = (uint32_t)(row * QSTR + kt * 16 + (lane >> 4) * 8) * 2u;
            ldmx4(qfh[kt], sb + SM_QH + off);
            ldmx4(qfl[kt], sb + SM_QL + off);
        }
    }

    float of[4][4];
    #pragma unroll
    for (int i = 0; i < 4; i++)
        #pragma unroll
        for (int p = 0; p < 4; p++) of[i][p] = 0.f;
    float es0 = 0.f, es1 = 0.f;

    const int kRow = (lane & 7) + ((lane >> 4) << 3);
    const int kColHalf = ((lane >> 3) & 1) * 8;
    const int vRow = lane & 15;            // key within 16-group
    const int vCol = (lane >> 4) * 8;      // dim sub-offset

    int st = 0;
    for (int m0 = 0; m0 < len; m0 += 64, st ^= 1) {
        cpa_wait<0>();
        __syncthreads();
        if (m0 + 64 < len) { load_tile(m0 + 64, st ^ 1); cpa_commit(); }

        const uint32_t bKH = sb + SM_ST0 + st * STAGEA;
        const uint32_t bKL = bKH + KBYTES;
        const uint32_t bVH = bKH + 2 * KBYTES;
        const uint32_t bVL = bVH + VBYTES;

        // ---- S = Q K^T (bf16x3) ----
        float sf[8][4];
        #pragma unroll
        for (int i = 0; i < 8; i++)
            #pragma unroll
            for (int p = 0; p < 4; p++) sf[i][p] = 0.f;
        #pragma unroll
        for (int kt = 0; kt < 2; kt++) {
            #pragma unroll
            for (int g2 = 0; g2 < 4; g2++) {
                uint32_t off = (uint32_t)((g2 * 16 + kRow) * KSTR + kt * 16 + kColHalf) * 2u;
                uint32_t kbh[4], kbl[4];
                ldmx4(kbh, bKH + off);
                ldmx4(kbl, bKL + off);
                mma_bf16(sf[g2*2],   qfh[kt], kbh[0], kbh[1]);
                mma_bf16(sf[g2*2],   qfh[kt], kbl[0], kbl[1]);
                mma_bf16(sf[g2*2],   qfl[kt], kbh[0], kbh[1]);
                mma_bf16(sf[g2*2+1], qfh[kt], kbh[2], kbh[3]);
                mma_bf16(sf[g2*2+1], qfh[kt], kbl[2], kbl[3]);
                mma_bf16(sf[g2*2+1], qfl[kt], kbh[2], kbh[3]);
            }
        }

        // ---- exp + split into P fragments ----
        uint32_t ph[8], phb[8], pl[8], plb[8];
        #pragma unroll
        for (int ni = 0; ni < 8; ni++) {
            int k0 = m0 + ni * 8 + ((lane & 3) << 1);
            float e0 = (k0     < len) ? __expf(sf[ni][0] * 0.0625f) : 0.f;
            float e1 = (k0 + 1 < len) ? __expf(sf[ni][1] * 0.0625f) : 0.f;
            float e2 = (k0     < len) ? __expf(sf[ni][2] * 0.0625f) : 0.f;
            float e3 = (k0 + 1 < len) ? __expf(sf[ni][3] * 0.0625f) : 0.f;
            es0 += e0 + e1; es1 += e2 + e3;
            uint32_t h0 = packbf(e0, e1), h1 = packbf(e2, e3);
            ph[ni] = h0; phb[ni] = h1;
            pl[ni]  = packbf(e0 - bflo_f(h0), e1 - bfhi_f(h0));
            plb[ni] = packbf(e2 - bflo_f(h1), e3 - bfhi_f(h1));
        }

        // ---- O += P V (bf16x3), V row-major + ldmatrix.trans ----
        #pragma unroll
        for (int kt2 = 0; kt2 < 4; kt2++) {
            uint32_t pa_h[4] = { ph[2*kt2], phb[2*kt2], ph[2*kt2+1], phb[2*kt2+1] };
            uint32_t pa_l[4] = { pl[2*kt2], plb[2*kt2], pl[2*kt2+1], plb[2*kt2+1] };
            #pragma unroll
            for (int g2 = 0; g2 < 2; g2++) {
                uint32_t off = (uint32_t)((kt2 * 16 + vRow) * VSTR2 + g2 * 16 + vCol) * 2u;
                uint32_t vbh[4], vbl[4];
                ldmx4t(vbh, bVH + off);
                ldmx4t(vbl, bVL + off);
                mma_bf16(of[g2*2],   pa_h, vbh[0], vbh[1]);
                mma_bf16(of[g2*2],   pa_h, vbl[0], vbl[1]);
                mma_bf16(of[g2*2],   pa_l, vbh[0], vbh[1]);
                mma_bf16(of[g2*2+1], pa_h, vbh[2], vbh[3]);
                mma_bf16(of[g2*2+1], pa_h, vbl[2], vbl[3]);
                mma_bf16(of[g2*2+1], pa_l, vbh[2], vbh[3]);
            }
        }
    }

    es0 += __shfl_xor_sync(0xFFFFFFFFu, es0, 1);
    es0 += __shfl_xor_sync(0xFFFFFFFFu, es0, 2);
    es1 += __shfl_xor_sync(0xFFFFFFFFu, es1, 1);
    es1 += __shfl_xor_sync(0xFFFFFFFFu, es1, 2);
    const float inv0 = 1.f / (es0 + 1e-15f);
    const float inv1 = 1.f / (es1 + 1e-15f);

    const int n0 = qt * 128 + w * 16 + (lane >> 2);
    const int n1 = n0 + 8;
    const bool a0 = n0 < len, a1 = n1 < len;
    #pragma unroll
    for (int ni = 0; ni < 4; ni++) {
        int col = h * HD + ni * 8 + ((lane & 3) << 1);
        float2 q0 = *(const float2*)&qres[((size_t)b * NN + n0) * DD + col];
        float2 q1 = *(const float2*)&qres[((size_t)b * NN + n1) * DD + col];
        float2 o0, o1;
        o0.x = a0 ? (q0.x + of[ni][0] * inv0) : 0.f;
        o0.y = a0 ? (q0.y + of[ni][1] * inv0) : 0.f;
        o1.x = a1 ? (q1.x + of[ni][2] * inv1) : 0.f;
        o1.y = a1 ? (q1.y + of[ni][3] * inv1) : 0.f;
        *(float2*)&o[((size_t)b * NN + n0) * DD + col] = o0;
        *(float2*)&o[((size_t)b * NN + n1) * DD + col] = o1;
    }
}

// ---------------- LayerNorm (optionally emits bf16 hi/lo split) ----------------
template<bool SPLIT>
__global__ void __launch_bounds__(256) ln_kernel(
    const float* __restrict__ x, const float* __restrict__ g,
    const float* __restrict__ b, float* __restrict__ y,
    __nv_bfloat16* __restrict__ yh, __nv_bfloat16* __restrict__ yl)
{
    const int row = blockIdx.x;
    const int t = threadIdx.x;
    __shared__ float sred[8];

    float v = x[(size_t)row * DD + t];

    float s = v;
    #pragma unroll
    for (int o = 16; o > 0; o >>= 1) s += __shfl_xor_sync(0xFFFFFFFFu, s, o);
    if ((t & 31) == 0) sred[t >> 5] = s;
    __syncthreads();
    float mu = 0.f;
    #pragma unroll
    for (int i = 0; i < 8; i++) mu += sred[i];
    mu *= (1.f / 256.f);

    float d = v - mu;
    float sq = d * d;
    #pragma unroll
    for (int o = 16; o > 0; o >>= 1) sq += __shfl_xor_sync(0xFFFFFFFFu, sq, o);
    __syncthreads();
    if ((t & 31) == 0) sred[t >> 5] = sq;
    __syncthreads();
    float var = 0.f;
    #pragma unroll
    for (int i = 0; i < 8; i++) var += sred[i];
    var *= (1.f / 256.f);

    float r = rsqrtf(var + 1e-5f);
    float out = d * r * g[t] + b[t];
    y[(size_t)row * DD + t] = out;
    if (SPLIT) {
        __nv_bfloat16 hh = __float2bfloat16(out);
        __nv_bfloat16 ll = __float2bfloat16(out - __bfloat162float(hh));
        yh[(size_t)row * DD + t] = hh;
        yl[(size_t)row * DD + t] = ll;
    }
}

// ---------------- launch ----------------
extern "C" void kernel_launch(void* const* d_in, const int* in_sizes, int n_in,
                              void* d_out, int out_size)
{
    const float* Q       = (const float*)d_in[0];
    const float* K       = (const float*)d_in[1];
    const int*   lengths = (const int*)  d_in[2];
    const float* Wq      = (const float*)d_in[3];
    const float* bq      = (const float*)d_in[4];
    const float* Wk      = (const float*)d_in[5];
    const float* bk      = (const float*)d_in[6];
    const float* Wv      = (const float*)d_in[7];
    const float* bv      = (const float*)d_in[8];
    const float* Wo      = (const float*)d_in[9];
    const float* bo      = (const float*)d_in[10];
    const float* g0      = (const float*)d_in[11];
    const float* b0      = (const float*)d_in[12];
    const float* g1      = (const float*)d_in[13];
    const float* b1      = (const float*)d_in[14];

    float *sq, *so, *st, *su;
    cudaGetSymbolAddress((void**)&sq, g_q);
    cudaGetSymbolAddress((void**)&so, g_o);
    cudaGetSymbolAddress((void**)&st, g_t);
    cudaGetSymbolAddress((void**)&su, g_u);
    __nv_bfloat16 *th, *tl;
    cudaGetSymbolAddress((void**)&th, g_th);
    cudaGetSymbolAddress((void**)&tl, g_tl);

    static int cfg = 0;
    if (!cfg) {
        cudaFuncSetAttribute(hgemm_kernel<0>, cudaFuncAttributeMaxDynamicSharedMemorySize, GEMM_SMEM2);
        cudaFuncSetAttribute(hgemm_kernel<1>, cudaFuncAttributeMaxDynamicSharedMemorySize, GEMM_SMEM2);
        cudaFuncSetAttribute(attn_hmma_kernel, cudaFuncAttributeMaxDynamicSharedMemorySize, SM_ATTN2);
        cfg = 1;
    }

    const int n4 = ELEMS / 4;
    split2_kernel<<<dim3((n4 + 255) / 256, 2), 256>>>((const float4*)Q, (const float4*)K, n4);
    wsplit4_kernel<<<dim3(64, 4), 256>>>(Wq, Wk, Wv, Wo);

    hgemm_kernel<0><<<dim3(ROWS / 128, DD / 128, 3), 256, GEMM_SMEM2>>>(bq, bk, bv, bo, lengths);

    attn_hmma_kernel<<<dim3(NN / 128, HH, BB), 256, SM_ATTN2>>>(sq, lengths, so);

    ln_kernel<true><<<ROWS, 256>>>(so, g0, b0, st, th, tl);

    hgemm_kernel<1><<<dim3(ROWS / 128, DD / 128, 1), 256, GEMM_SMEM2>>>(bq, bk, bv, bo, lengths);

    ln_kernel<false><<<ROWS, 256>>>(su, g1, b1, (float*)d_out, nullptr, nullptr);
}

// round 10
// speedup vs baseline: 2.3131x; 1.0276x over previous
#include <cuda_runtime.h>
#include <cuda_bf16.h>
#include <math.h>
#include <stdint.h>

#define BB 8
#define NN 1024
#define DD 256
#define HH 8
#define HD 32
#define ROWS (BB*NN)          // 8192
#define ELEMS (ROWS*DD)       // 2097152

typedef unsigned long long u64;

// -------- scratch (static device globals; no allocation) --------
__device__ float g_o[ELEMS];      // attention output
__device__ float g_t[ELEMS];      // ln0 out
__device__ float g_u[ELEMS];      // mlp out

__device__ __nv_bfloat16 g_qih[ELEMS];   // input splits (GEMM A operands)
__device__ __nv_bfloat16 g_qil[ELEMS];
__device__ __nv_bfloat16 g_kih[ELEMS];
__device__ __nv_bfloat16 g_kil[ELEMS];
__device__ __nv_bfloat16 g_th[ELEMS];    // ln0 split
__device__ __nv_bfloat16 g_tl[ELEMS];

// attention operand splits (produced by projection epilogues)
__device__ __nv_bfloat16 g_aqh[ELEMS]; __device__ __nv_bfloat16 g_aql[ELEMS];
__device__ __nv_bfloat16 g_akh[ELEMS]; __device__ __nv_bfloat16 g_akl[ELEMS];
__device__ __nv_bfloat16 g_avh[ELEMS]; __device__ __nv_bfloat16 g_avl[ELEMS];

#define WSZ (DD*DD)
__device__ __nv_bfloat16 g_wqh[WSZ]; __device__ __nv_bfloat16 g_wql[WSZ];
__device__ __nv_bfloat16 g_wkh[WSZ]; __device__ __nv_bfloat16 g_wkl[WSZ];
__device__ __nv_bfloat16 g_wvh[WSZ]; __device__ __nv_bfloat16 g_wvl[WSZ];
__device__ __nv_bfloat16 g_woh[WSZ]; __device__ __nv_bfloat16 g_wol[WSZ];

// ---------- helpers ----------
__device__ __forceinline__ void ldmx4(uint32_t* r, uint32_t addr) {
    asm volatile("ldmatrix.sync.aligned.m8n8.x4.shared.b16 {%0,%1,%2,%3}, [%4];"
                 : "=r"(r[0]), "=r"(r[1]), "=r"(r[2]), "=r"(r[3]) : "r"(addr));
}
__device__ __forceinline__ void ldmx4t(uint32_t* r, uint32_t addr) {
    asm volatile("ldmatrix.sync.aligned.m8n8.x4.trans.shared.b16 {%0,%1,%2,%3}, [%4];"
                 : "=r"(r[0]), "=r"(r[1]), "=r"(r[2]), "=r"(r[3]) : "r"(addr));
}
__device__ __forceinline__ void mma_bf16(float* c, const uint32_t* a, uint32_t b0, uint32_t b1) {
    asm volatile(
        "mma.sync.aligned.m16n8k16.row.col.f32.bf16.bf16.f32 "
        "{%0,%1,%2,%3}, {%4,%5,%6,%7}, {%8,%9}, {%0,%1,%2,%3};"
        : "+f"(c[0]), "+f"(c[1]), "+f"(c[2]), "+f"(c[3])
        : "r"(a[0]), "r"(a[1]), "r"(a[2]), "r"(a[3]), "r"(b0), "r"(b1));
}
__device__ __forceinline__ uint32_t packbf(float lo, float hi) {
    uint32_t r;
    asm("cvt.rn.bf16x2.f32 %0, %1, %2;" : "=r"(r) : "f"(hi), "f"(lo));
    return r;
}
__device__ __forceinline__ float bflo_f(uint32_t p) { return __uint_as_float(p << 16); }
__device__ __forceinline__ float bfhi_f(uint32_t p) { return __uint_as_float(p & 0xFFFF0000u); }

__device__ __forceinline__ void cpa16(uint32_t saddr, const void* g) {
    asm volatile("cp.async.cg.shared.global [%0], [%1], 16;" :: "r"(saddr), "l"(g));
}
__device__ __forceinline__ void cpa_commit() {
    asm volatile("cp.async.commit_group;" ::: "memory");
}
template<int N>
__device__ __forceinline__ void cpa_wait() {
    asm volatile("cp.async.wait_group %0;" :: "n"(N) : "memory");
}

// ================= input split (Q and K in one launch) =================
__global__ void __launch_bounds__(256) split2_kernel(
    const float4* __restrict__ Q, const float4* __restrict__ K, int n4)
{
    int i = blockIdx.x * 256 + threadIdx.x;
    if (i >= n4) return;
    const float4* x = blockIdx.y ? K : Q;
    uint2* hi = blockIdx.y ? (uint2*)g_kih : (uint2*)g_qih;
    uint2* lo = blockIdx.y ? (uint2*)g_kil : (uint2*)g_qil;
    float4 v = x[i];
    uint32_t h0 = packbf(v.x, v.y), h1 = packbf(v.z, v.w);
    uint32_t l0 = packbf(v.x - bflo_f(h0), v.y - bfhi_f(h0));
    uint32_t l1 = packbf(v.z - bflo_f(h1), v.w - bfhi_f(h1));
    uint2 hu, lu; hu.x = h0; hu.y = h1; lu.x = l0; lu.y = l1;
    hi[i] = hu; lo[i] = lu;
}

// ================= fused coalesced weight transpose+split =================
__global__ void __launch_bounds__(256) wsplit4_kernel(
    const float* __restrict__ Wq, const float* __restrict__ Wk,
    const float* __restrict__ Wv, const float* __restrict__ Wo)
{
    __shared__ float tile[32][33];
    const float* W; __nv_bfloat16 *th, *tl;
    switch (blockIdx.y) {
        case 0: W = Wq; th = g_wqh; tl = g_wql; break;
        case 1: W = Wk; th = g_wkh; tl = g_wkl; break;
        case 2: W = Wv; th = g_wvh; tl = g_wvl; break;
        default: W = Wo; th = g_woh; tl = g_wol; break;
    }
    const int tx = threadIdx.x & 31, ty = threadIdx.x >> 5;
    const int tR = (blockIdx.x & 7) * 32, tC = (blockIdx.x >> 3) * 32;
    #pragma unroll
    for (int j = 0; j < 4; j++)
        tile[ty + j * 8][tx] = W[(tR + ty + j * 8) * DD + tC + tx];
    __syncthreads();
    #pragma unroll
    for (int j = 0; j < 4; j++) {
        int n = tC + ty + j * 8, k = tR + tx;
        float w = tile[tx][ty + j * 8];
        __nv_bfloat16 h = __float2bfloat16(w);
        th[n * DD + k] = h;
        tl[n * DD + k] = __float2bfloat16(w - __bfloat162float(h));
    }
}

// ================= pipelined HMMA GEMM =================
#define PSTR 72
#define TILEB (128 * PSTR * 2)
#define STAGE (4 * TILEB)
#define GEMM_SMEM2 (2 * STAGE)

template<int MODE>
__global__ void __launch_bounds__(256) hgemm_kernel(
    const float* __restrict__ bq, const float* __restrict__ bk,
    const float* __restrict__ bv, const float* __restrict__ bo,
    const int* __restrict__ lengths)
{
    extern __shared__ char smc[];
    const int tid = threadIdx.x, wid = tid >> 5, lane = tid & 31;
    const int brow = blockIdx.x * 128, bcol = blockIdx.y * 128;
    const int wm = wid & 1, wn = wid >> 1;

    const __nv_bfloat16 *Ah_, *Al_, *Bh_, *Bl_;
    const float *bias;
    const float *res = nullptr;
    float* C = nullptr;
    __nv_bfloat16 *Ch = nullptr, *Cl = nullptr;
    if (MODE == 0) {
        switch (blockIdx.z) {
            case 0:  Ah_ = g_qih; Al_ = g_qil; Bh_ = g_wqh; Bl_ = g_wql;
                     bias = bq; Ch = g_aqh; Cl = g_aql; break;
            case 1:  Ah_ = g_kih; Al_ = g_kil; Bh_ = g_wkh; Bl_ = g_wkl;
                     bias = bk; Ch = g_akh; Cl = g_akl; break;
            default: Ah_ = g_kih; Al_ = g_kil; Bh_ = g_wvh; Bl_ = g_wvl;
                     bias = bv; Ch = g_avh; Cl = g_avl; break;
        }
    } else {
        Ah_ = g_th; Al_ = g_tl; Bh_ = g_woh; Bl_ = g_wol;
        bias = bo; res = g_t; C = g_u;
    }

    if (MODE == 0) {
        const int blen = lengths[brow >> 10];
        if ((brow & 1023) >= blen) {
            uint4 zu = make_uint4(0u, 0u, 0u, 0u);
            #pragma unroll
            for (int i = 0; i < 8; i++) {
                int idx = tid + i * 256;
                int r = idx >> 4, c8 = idx & 15;
                *(uint4*)&Ch[(size_t)(brow + r) * DD + bcol + c8 * 8] = zu;
                *(uint4*)&Cl[(size_t)(brow + r) * DD + bcol + c8 * 8] = zu;
            }
            return;
        }
    }

    const uint32_t sbu = (uint32_t)__cvta_generic_to_shared(smc);
    const int ldr = tid >> 3;
    const int ldc = tid & 7;

    auto load_chunk = [&](int ch, int st) {
        const int kc0 = ch * 64;
        const uint32_t s0 = sbu + st * STAGE;
        #pragma unroll
        for (int i = 0; i < 4; i++) {
            int r = ldr + i * 32;
            size_t ga = (size_t)(brow + r) * DD + kc0 + ldc * 8;
            size_t gb = (size_t)(bcol + r) * DD + kc0 + ldc * 8;
            uint32_t so = (uint32_t)(r * PSTR + ldc * 8) * 2u;
            cpa16(s0 + 0 * TILEB + so, Ah_ + ga);
            cpa16(s0 + 1 * TILEB + so, Al_ + ga);
            cpa16(s0 + 2 * TILEB + so, Bh_ + gb);
            cpa16(s0 + 3 * TILEB + so, Bl_ + gb);
        }
    };

    float acc[4][4][4];
    #pragma unroll
    for (int i = 0; i < 4; i++)
        #pragma unroll
        for (int j = 0; j < 4; j++)
            #pragma unroll
            for (int p = 0; p < 4; p++) acc[i][j][p] = 0.f;

    const int aRow = wm * 64 + (lane & 15);
    const int aK   = (lane >> 4) * 8;
    const int bRow = wn * 32 + (lane & 7) + (lane >> 4) * 8;
    const int bK   = ((lane >> 3) & 1) * 8;

    load_chunk(0, 0);
    cpa_commit();

    for (int ch = 0; ch < 4; ch++) {
        if (ch < 3) { load_chunk(ch + 1, (ch + 1) & 1); cpa_commit(); }
        if (ch < 3) cpa_wait<1>(); else cpa_wait<0>();
        __syncthreads();

        const uint32_t stb = sbu + (ch & 1) * STAGE;
        const uint32_t bAh = stb, bAl = stb + TILEB, bBh = stb + 2 * TILEB, bBl = stb + 3 * TILEB;

        #pragma unroll
        for (int ks = 0; ks < 4; ks++) {
            const int kk = ks * 16;
            uint32_t ah[4][4], al[4][4], bh[2][4], bl[2][4];
            #pragma unroll
            for (int mi = 0; mi < 4; mi++) {
                uint32_t off = (uint32_t)((aRow + mi * 16) * PSTR + kk + aK) * 2u;
                ldmx4(ah[mi], bAh + off);
                ldmx4(al[mi], bAl + off);
            }
            #pragma unroll
            for (int n2 = 0; n2 < 2; n2++) {
                uint32_t off = (uint32_t)((bRow + n2 * 16) * PSTR + kk + bK) * 2u;
                ldmx4(bh[n2], bBh + off);
                ldmx4(bl[n2], bBl + off);
            }
            #pragma unroll
            for (int mi = 0; mi < 4; mi++)
                #pragma unroll
                for (int ni = 0; ni < 4; ni++) {
                    uint32_t bh0 = bh[ni >> 1][(ni & 1) * 2], bh1 = bh[ni >> 1][(ni & 1) * 2 + 1];
                    uint32_t bl0 = bl[ni >> 1][(ni & 1) * 2], bl1 = bl[ni >> 1][(ni & 1) * 2 + 1];
                    mma_bf16(acc[mi][ni], ah[mi], bh0, bh1);
                    mma_bf16(acc[mi][ni], ah[mi], bl0, bl1);
                    mma_bf16(acc[mi][ni], al[mi], bh0, bh1);
                }
        }
        __syncthreads();
    }

    const int blen = (MODE == 0) ? lengths[brow >> 10] : 0;
    #pragma unroll
    for (int mi = 0; mi < 4; mi++) {
        int r0 = brow + wm * 64 + mi * 16 + (lane >> 2);
        int r1 = r0 + 8;
        #pragma unroll
        for (int ni = 0; ni < 4; ni++) {
            int col = bcol + wn * 32 + ni * 8 + (lane & 3) * 2;
            float b0 = bias[col], b1 = bias[col + 1];
            float c0 = acc[mi][ni][0] + b0, c1 = acc[mi][ni][1] + b1;
            float c2 = acc[mi][ni][2] + b0, c3 = acc[mi][ni][3] + b1;
            if (MODE == 0) {
                if ((r0 & 1023) >= blen) { c0 = 0.f; c1 = 0.f; }
                if ((r1 & 1023) >= blen) { c2 = 0.f; c3 = 0.f; }
                uint32_t h0 = packbf(c0, c1), h1 = packbf(c2, c3);
                uint32_t l0 = packbf(c0 - bflo_f(h0), c1 - bfhi_f(h0));
                uint32_t l1 = packbf(c2 - bflo_f(h1), c3 - bfhi_f(h1));
                *(uint32_t*)&Ch[(size_t)r0 * DD + col] = h0;
                *(uint32_t*)&Cl[(size_t)r0 * DD + col] = l0;
                *(uint32_t*)&Ch[(size_t)r1 * DD + col] = h1;
                *(uint32_t*)&Cl[(size_t)r1 * DD + col] = l1;
            } else {
                float2 x0 = *(const float2*)&res[(size_t)r0 * DD + col];
                float2 x1 = *(const float2*)&res[(size_t)r1 * DD + col];
                c0 = x0.x + fmaxf(c0, 0.f); c1 = x0.y + fmaxf(c1, 0.f);
                c2 = x1.x + fmaxf(c2, 0.f); c3 = x1.y + fmaxf(c3, 0.f);
                *(float2*)&C[(size_t)r0 * DD + col] = make_float2(c0, c1);
                *(float2*)&C[(size_t)r1 * DD + col] = make_float2(c2, c3);
            }
        }
    }
}

// ================= HMMA attention: dual PV accumulators + interior fast path ============
#define QSTR 56
#define KSTR 56
#define VSTR2 40
#define SM_QH 0
#define SM_QL (SM_QH + 128*QSTR*2)      // 14336
#define SM_ST0 (SM_QL + 128*QSTR*2)     // 28672
#define KBYTES (64*KSTR*2)              // 7168
#define VBYTES (64*VSTR2*2)             // 5120
#define STAGEA (2*KBYTES + 2*VBYTES)    // 24576
#define SM_ATTN2 (SM_ST0 + 2*STAGEA)    // 77824

__global__ void __launch_bounds__(256) attn_hmma_kernel(
    const int* __restrict__ lengths, float* __restrict__ o)
{
    extern __shared__ char smc[];
    const int qt = blockIdx.x, h = blockIdx.y, b = blockIdx.z;
    const int len = lengths[b];
    const int tid = threadIdx.x, w = tid >> 5, lane = tid & 31;

    if (qt * 128 >= len) {
        float4 z = make_float4(0.f, 0.f, 0.f, 0.f);
        #pragma unroll
        for (int i = 0; i < 4; i++) {
            int idx = tid + i * 256;
            int r = idx >> 3, c4 = idx & 7;
            *(float4*)&o[((size_t)b * NN + qt * 128 + r) * DD + h * HD + c4 * 4] = z;
        }
        return;
    }

    const uint32_t sb = (uint32_t)__cvta_generic_to_shared(smc);

    const int ldr = tid >> 2, ldc4 = tid & 3;
    auto load_tile = [&](int m0, int st) {
        int row = m0 + ldr; if (row >= len) row = len - 1;
        size_t g = ((size_t)b * NN + row) * DD + h * HD + ldc4 * 8;
        uint32_t s0 = sb + SM_ST0 + st * STAGEA;
        cpa16(s0 + (uint32_t)(ldr * KSTR + ldc4 * 8) * 2u,           g_akh + g);
        cpa16(s0 + KBYTES + (uint32_t)(ldr * KSTR + ldc4 * 8) * 2u,  g_akl + g);
        cpa16(s0 + 2*KBYTES + (uint32_t)(ldr * VSTR2 + ldc4 * 8) * 2u,          g_avh + g);
        cpa16(s0 + 2*KBYTES + VBYTES + (uint32_t)(ldr * VSTR2 + ldc4 * 8) * 2u, g_avl + g);
    };

    load_tile(0, 0);
    cpa_commit();

    {   // Q tile (128 x 32) hi/lo
        const size_t gq = ((size_t)b * NN + qt * 128) * DD + h * HD;
        #pragma unroll
        for (int i = 0; i < 2; i++) {
            int idx = tid + i * 256;
            int r = idx >> 2, c4 = idx & 3;
            *(uint4*)(smc + SM_QH + (r * QSTR + c4 * 8) * 2) = *(const uint4*)(g_aqh + gq + (size_t)r * DD + c4 * 8);
            *(uint4*)(smc + SM_QL + (r * QSTR + c4 * 8) * 2) = *(const uint4*)(g_aql + gq + (size_t)r * DD + c4 * 8);
        }
    }
    __syncthreads();

    uint32_t qfh[2][4], qfl[2][4];
    {
        int row = w * 16 + (lane & 15);
        #pragma unroll
        for (int kt = 0; kt < 2; kt++) {
            uint32_t off = (uint32_t)(row * QSTR + kt * 16 + (lane >> 4) * 8) * 2u;
            ldmx4(qfh[kt], sb + SM_QH + off);
            ldmx4(qfl[kt], sb + SM_QL + off);
        }
    }

    float ofA[4][4], ofB[4][4];
    #pragma unroll
    for (int i = 0; i < 4; i++)
        #pragma unroll
        for (int p = 0; p < 4; p++) { ofA[i][p] = 0.f; ofB[i][p] = 0.f; }
    float es0 = 0.f, es1 = 0.f;

    const int kRow = (lane & 7) + ((lane >> 4) << 3);
    const int kColHalf = ((lane >> 3) & 1) * 8;
    const int vRow = lane & 15;
    const int vCol = (lane >> 4) * 8;

    int st = 0;
    for (int m0 = 0; m0 < len; m0 += 64, st ^= 1) {
        cpa_wait<0>();
        __syncthreads();
        if (m0 + 64 < len) { load_tile(m0 + 64, st ^ 1); cpa_commit(); }

        const uint32_t bKH = sb + SM_ST0 + st * STAGEA;
        const uint32_t bKL = bKH + KBYTES;
        const uint32_t bVH = bKH + 2 * KBYTES;
        const uint32_t bVL = bVH + VBYTES;

        // ---- S = Q K^T (bf16x3) ----
        float sf[8][4];
        #pragma unroll
        for (int i = 0; i < 8; i++)
            #pragma unroll
            for (int p = 0; p < 4; p++) sf[i][p] = 0.f;
        #pragma unroll
        for (int kt = 0; kt < 2; kt++) {
            #pragma unroll
            for (int g2 = 0; g2 < 4; g2++) {
                uint32_t off = (uint32_t)((g2 * 16 + kRow) * KSTR + kt * 16 + kColHalf) * 2u;
                uint32_t kbh[4], kbl[4];
                ldmx4(kbh, bKH + off);
                ldmx4(kbl, bKL + off);
                mma_bf16(sf[g2*2],   qfh[kt], kbh[0], kbh[1]);
                mma_bf16(sf[g2*2],   qfh[kt], kbl[0], kbl[1]);
                mma_bf16(sf[g2*2],   qfl[kt], kbh[0], kbh[1]);
                mma_bf16(sf[g2*2+1], qfh[kt], kbh[2], kbh[3]);
                mma_bf16(sf[g2*2+1], qfh[kt], kbl[2], kbl[3]);
                mma_bf16(sf[g2*2+1], qfl[kt], kbh[2], kbh[3]);
            }
        }

        // ---- exp + split into P fragments (fast path when tile fully valid) ----
        uint32_t ph[8], phb[8], pl[8], plb[8];
        if (m0 + 64 <= len) {
            #pragma unroll
            for (int ni = 0; ni < 8; ni++) {
                float e0 = __expf(sf[ni][0] * 0.0625f);
                float e1 = __expf(sf[ni][1] * 0.0625f);
                float e2 = __expf(sf[ni][2] * 0.0625f);
                float e3 = __expf(sf[ni][3] * 0.0625f);
                es0 += e0 + e1; es1 += e2 + e3;
                uint32_t h0 = packbf(e0, e1), h1 = packbf(e2, e3);
                ph[ni] = h0; phb[ni] = h1;
                pl[ni]  = packbf(e0 - bflo_f(h0), e1 - bfhi_f(h0));
                plb[ni] = packbf(e2 - bflo_f(h1), e3 - bfhi_f(h1));
            }
        } else {
            #pragma unroll
            for (int ni = 0; ni < 8; ni++) {
                int k0 = m0 + ni * 8 + ((lane & 3) << 1);
                float e0 = (k0     < len) ? __expf(sf[ni][0] * 0.0625f) : 0.f;
                float e1 = (k0 + 1 < len) ? __expf(sf[ni][1] * 0.0625f) : 0.f;
                float e2 = (k0     < len) ? __expf(sf[ni][2] * 0.0625f) : 0.f;
                float e3 = (k0 + 1 < len) ? __expf(sf[ni][3] * 0.0625f) : 0.f;
                es0 += e0 + e1; es1 += e2 + e3;
                uint32_t h0 = packbf(e0, e1), h1 = packbf(e2, e3);
                ph[ni] = h0; phb[ni] = h1;
                pl[ni]  = packbf(e0 - bflo_f(h0), e1 - bfhi_f(h0));
                plb[ni] = packbf(e2 - bflo_f(h1), e3 - bfhi_f(h1));
            }
        }

        // ---- O += P V (bf16x3), dual accumulator banks for ILP ----
        #pragma unroll
        for (int kt2 = 0; kt2 < 4; kt2++) {
            uint32_t pa_h[4] = { ph[2*kt2], phb[2*kt2], ph[2*kt2+1], phb[2*kt2+1] };
            uint32_t pa_l[4] = { pl[2*kt2], plb[2*kt2], pl[2*kt2+1], plb[2*kt2+1] };
            #pragma unroll
            for (int g2 = 0; g2 < 2; g2++) {
                uint32_t off = (uint32_t)((kt2 * 16 + vRow) * VSTR2 + g2 * 16 + vCol) * 2u;
                uint32_t vbh[4], vbl[4];
                ldmx4t(vbh, bVH + off);
                ldmx4t(vbl, bVL + off);
                // balanced 6/6 split of the 12 per-acc serial MMAs
                mma_bf16(ofA[g2*2],   pa_h, vbh[0], vbh[1]);
                mma_bf16(ofB[g2*2],   pa_h, vbl[0], vbl[1]);
                mma_bf16(ofA[g2*2+1], pa_h, vbh[2], vbh[3]);
                mma_bf16(ofB[g2*2+1], pa_h, vbl[2], vbl[3]);
                if (kt2 & 1) {
                    mma_bf16(ofA[g2*2],   pa_l, vbh[0], vbh[1]);
                    mma_bf16(ofB[g2*2+1], pa_l, vbh[2], vbh[3]);
                } else {
                    mma_bf16(ofB[g2*2],   pa_l, vbh[0], vbh[1]);
                    mma_bf16(ofA[g2*2+1], pa_l, vbh[2], vbh[3]);
                }
            }
        }
    }

    es0 += __shfl_xor_sync(0xFFFFFFFFu, es0, 1);
    es0 += __shfl_xor_sync(0xFFFFFFFFu, es0, 2);
    es1 += __shfl_xor_sync(0xFFFFFFFFu, es1, 1);
    es1 += __shfl_xor_sync(0xFFFFFFFFu, es1, 2);
    const float inv0 = 1.f / (es0 + 1e-15f);
    const float inv1 = 1.f / (es1 + 1e-15f);

    const int n0 = qt * 128 + w * 16 + (lane >> 2);
    const int n1 = n0 + 8;
    const bool a0 = n0 < len, a1 = n1 < len;
    const int r0l = w * 16 + (lane >> 2);    // local q rows in smem
    #pragma unroll
    for (int ni = 0; ni < 4; ni++) {
        int ci = ni * 8 + ((lane & 3) << 1);             // col within 32
        int col = h * HD + ci;
        // residual q from smem (qh + ql reconstruction)
        uint32_t uh0 = *(uint32_t*)(smc + SM_QH + (r0l * QSTR + ci) * 2);
        uint32_t ul0 = *(uint32_t*)(smc + SM_QL + (r0l * QSTR + ci) * 2);
        uint32_t uh1 = *(uint32_t*)(smc + SM_QH + ((r0l + 8) * QSTR + ci) * 2);
        uint32_t ul1 = *(uint32_t*)(smc + SM_QL + ((r0l + 8) * QSTR + ci) * 2);
        float2 o0, o1;
        o0.x = a0 ? (bflo_f(uh0) + bflo_f(ul0) + (ofA[ni][0] + ofB[ni][0]) * inv0) : 0.f;
        o0.y = a0 ? (bfhi_f(uh0) + bfhi_f(ul0) + (ofA[ni][1] + ofB[ni][1]) * inv0) : 0.f;
        o1.x = a1 ? (bflo_f(uh1) + bflo_f(ul1) + (ofA[ni][2] + ofB[ni][2]) * inv1) : 0.f;
        o1.y = a1 ? (bfhi_f(uh1) + bfhi_f(ul1) + (ofA[ni][3] + ofB[ni][3]) * inv1) : 0.f;
        *(float2*)&o[((size_t)b * NN + n0) * DD + col] = o0;
        *(float2*)&o[((size_t)b * NN + n1) * DD + col] = o1;
    }
}

// ---------------- LayerNorm (optionally emits bf16 hi/lo split) ----------------
template<bool SPLIT>
__global__ void __launch_bounds__(256) ln_kernel(
    const float* __restrict__ x, const float* __restrict__ g,
    const float* __restrict__ b, float* __restrict__ y,
    __nv_bfloat16* __restrict__ yh, __nv_bfloat16* __restrict__ yl)
{
    const int row = blockIdx.x;
    const int t = threadIdx.x;
    __shared__ float sred[8];

    float v = x[(size_t)row * DD + t];

    float s = v;
    #pragma unroll
    for (int o = 16; o > 0; o >>= 1) s += __shfl_xor_sync(0xFFFFFFFFu, s, o);
    if ((t & 31) == 0) sred[t >> 5] = s;
    __syncthreads();
    float mu = 0.f;
    #pragma unroll
    for (int i = 0; i < 8; i++) mu += sred[i];
    mu *= (1.f / 256.f);

    float d = v - mu;
    float sq = d * d;
    #pragma unroll
    for (int o = 16; o > 0; o >>= 1) sq += __shfl_xor_sync(0xFFFFFFFFu, sq, o);
    __syncthreads();
    if ((t & 31) == 0) sred[t >> 5] = sq;
    __syncthreads();
    float var = 0.f;
    #pragma unroll
    for (int i = 0; i < 8; i++) var += sred[i];
    var *= (1.f / 256.f);

    float r = rsqrtf(var + 1e-5f);
    float out = d * r * g[t] + b[t];
    y[(size_t)row * DD + t] = out;
    if (SPLIT) {
        __nv_bfloat16 hh = __float2bfloat16(out);
        __nv_bfloat16 ll = __float2bfloat16(out - __bfloat162float(hh));
        yh[(size_t)row * DD + t] = hh;
        yl[(size_t)row * DD + t] = ll;
    }
}

// ---------------- launch ----------------
extern "C" void kernel_launch(void* const* d_in, const int* in_sizes, int n_in,
                              void* d_out, int out_size)
{
    const float* Q       = (const float*)d_in[0];
    const float* K       = (const float*)d_in[1];
    const int*   lengths = (const int*)  d_in[2];
    const float* Wq      = (const float*)d_in[3];
    const float* bq      = (const float*)d_in[4];
    const float* Wk      = (const float*)d_in[5];
    const float* bk      = (const float*)d_in[6];
    const float* Wv      = (const float*)d_in[7];
    const float* bv      = (const float*)d_in[8];
    const float* Wo      = (const float*)d_in[9];
    const float* bo      = (const float*)d_in[10];
    const float* g0      = (const float*)d_in[11];
    const float* b0      = (const float*)d_in[12];
    const float* g1      = (const float*)d_in[13];
    const float* b1      = (const float*)d_in[14];

    float *so, *st, *su;
    cudaGetSymbolAddress((void**)&so, g_o);
    cudaGetSymbolAddress((void**)&st, g_t);
    cudaGetSymbolAddress((void**)&su, g_u);
    __nv_bfloat16 *th, *tl;
    cudaGetSymbolAddress((void**)&th, g_th);
    cudaGetSymbolAddress((void**)&tl, g_tl);

    static int cfg = 0;
    if (!cfg) {
        cudaFuncSetAttribute(hgemm_kernel<0>, cudaFuncAttributeMaxDynamicSharedMemorySize, GEMM_SMEM2);
        cudaFuncSetAttribute(hgemm_kernel<1>, cudaFuncAttributeMaxDynamicSharedMemorySize, GEMM_SMEM2);
        cudaFuncSetAttribute(attn_hmma_kernel, cudaFuncAttributeMaxDynamicSharedMemorySize, SM_ATTN2);
        cfg = 1;
    }

    const int n4 = ELEMS / 4;
    split2_kernel<<<dim3((n4 + 255) / 256, 2), 256>>>((const float4*)Q, (const float4*)K, n4);
    wsplit4_kernel<<<dim3(64, 4), 256>>>(Wq, Wk, Wv, Wo);

    hgemm_kernel<0><<<dim3(ROWS / 128, DD / 128, 3), 256, GEMM_SMEM2>>>(bq, bk, bv, bo, lengths);

    attn_hmma_kernel<<<dim3(NN / 128, HH, BB), 256, SM_ATTN2>>>(lengths, so);

    ln_kernel<true><<<ROWS, 256>>>(so, g0, b0, st, th, tl);

    hgemm_kernel<1><<<dim3(ROWS / 128, DD / 128, 1), 256, GEMM_SMEM2>>>(bq, bk, bv, bo, lengths);

    ln_kernel<false><<<ROWS, 256>>>(su, g1, b1, (float*)d_out, nullptr, nullptr);
}